// round 2
// baseline (speedup 1.0000x reference)
#include <cuda_runtime.h>
#include <math.h>

// Causal attention, B=16, N=2048, D=256, fp32.
// Flash-attention tiling: BQ=BK=64, one CTA per (batch, q-tile), 256 threads.
// Q/K/V tiles in padded smem (row stride 260 floats = 65 float4) for
// conflict-free LDS.128; P staged through smem between S-phase and PV-phase.

#define BQ 64
#define BK 64
#define DHEAD 256
#define S4 65          // tile row stride in float4 units (260 floats)
#define PSTR 65        // P row stride in floats

// smem floats: 3 tiles * 64*260 + P 64*65  = 49920 + 4160 = 54080 floats
// + 64 ints padding mask
#define SMEM_FLOATS (3 * 64 * 260 + 64 * 65)
#define SMEM_BYTES  (SMEM_FLOATS * 4 + 64 * 4)

__global__ __launch_bounds__(256, 1)
void attn_fa_fp32_kernel(const float* __restrict__ Q,
                         const float* __restrict__ K,
                         const float* __restrict__ V,
                         const int*   __restrict__ pm,
                         float* __restrict__ O,
                         int N)
{
    extern __shared__ float smem[];
    float* sQ = smem;                    // 64 x 260
    float* sK = sQ + 64 * 260;           // 64 x 260
    float* sV = sK + 64 * 260;           // 64 x 260
    float* sP = sV + 64 * 260;           // 64 x 65
    int*   sPm = (int*)(sP + 64 * 65);   // 64

    // Reverse q-tile order so the longest CTAs (largest qt) start first.
    const int qt = (gridDim.x - 1) - blockIdx.x;
    const int b  = blockIdx.y;
    const int tid = threadIdx.x;
    const int tx = tid & 15;
    const int ty = tid >> 4;

    const float scale = 0.0625f;  // 1/sqrt(256)

    // ---- Load Q tile (pre-scaled) ----
    {
        const float4* gQ = (const float4*)(Q + ((size_t)b * N + (size_t)qt * BQ) * DHEAD);
        float4* s4q = (float4*)sQ;
        #pragma unroll
        for (int i = 0; i < 16; i++) {
            int f = tid + i * 256;           // 0..4095 float4s
            int row = f >> 6, col = f & 63;
            float4 v = gQ[row * 64 + col];
            v.x *= scale; v.y *= scale; v.z *= scale; v.w *= scale;
            s4q[row * S4 + col] = v;
        }
    }

    float m[4], l[4];
    float Ofrag[4][16];
    #pragma unroll
    for (int i = 0; i < 4; i++) {
        m[i] = -INFINITY;
        l[i] = 0.0f;
        #pragma unroll
        for (int c = 0; c < 16; c++) Ofrag[i][c] = 0.0f;
    }

    for (int kt = 0; kt <= qt; kt++) {
        // ---- Load K, V tiles + padding mask ----
        {
            const float4* gK = (const float4*)(K + ((size_t)b * N + (size_t)kt * BK) * DHEAD);
            const float4* gV = (const float4*)(V + ((size_t)b * N + (size_t)kt * BK) * DHEAD);
            float4* s4k = (float4*)sK;
            float4* s4v = (float4*)sV;
            #pragma unroll
            for (int i = 0; i < 16; i++) {
                int f = tid + i * 256;
                int row = f >> 6, col = f & 63;
                s4k[row * S4 + col] = gK[row * 64 + col];
                s4v[row * S4 + col] = gV[row * 64 + col];
            }
            if (tid < 64) sPm[tid] = pm[(size_t)b * N + (size_t)kt * BK + tid];
        }
        __syncthreads();

        // ---- S = Qtile @ Ktile^T : rows ty+16i, cols tx+16j ----
        float S[4][4];
        #pragma unroll
        for (int i = 0; i < 4; i++)
            #pragma unroll
            for (int j = 0; j < 4; j++) S[i][j] = 0.0f;

        const float4* s4q = (const float4*)sQ;
        const float4* s4k = (const float4*)sK;
        #pragma unroll 4
        for (int d4 = 0; d4 < 64; d4++) {
            float4 qv[4], kv[4];
            #pragma unroll
            for (int i = 0; i < 4; i++) qv[i] = s4q[(ty + 16 * i) * S4 + d4];
            #pragma unroll
            for (int j = 0; j < 4; j++) kv[j] = s4k[(tx + 16 * j) * S4 + d4];
            #pragma unroll
            for (int i = 0; i < 4; i++)
                #pragma unroll
                for (int j = 0; j < 4; j++) {
                    S[i][j] += qv[i].x * kv[j].x;
                    S[i][j] += qv[i].y * kv[j].y;
                    S[i][j] += qv[i].z * kv[j].z;
                    S[i][j] += qv[i].w * kv[j].w;
                }
        }

        // ---- masks (causal only on the diagonal tile; padding always) ----
        const bool diag = (kt == qt);
        #pragma unroll
        for (int j = 0; j < 4; j++) {
            const int kloc = tx + 16 * j;
            const bool pmok = (sPm[kloc] != 0);
            #pragma unroll
            for (int i = 0; i < 4; i++) {
                const int qloc = ty + 16 * i;
                const bool ok = pmok && (!diag || (kloc <= qloc));
                if (!ok) S[i][j] = -INFINITY;
            }
        }

        // ---- online softmax (row reductions across the 16-lane half-warp) ----
        float alpha[4];
        #pragma unroll
        for (int i = 0; i < 4; i++) {
            float rmax = fmaxf(fmaxf(S[i][0], S[i][1]), fmaxf(S[i][2], S[i][3]));
            #pragma unroll
            for (int off = 8; off >= 1; off >>= 1)
                rmax = fmaxf(rmax, __shfl_xor_sync(0xffffffffu, rmax, off));
            const float mnew = fmaxf(m[i], rmax);
            alpha[i] = __expf(m[i] - mnew);
            m[i] = mnew;
            float rsum = 0.0f;
            #pragma unroll
            for (int j = 0; j < 4; j++) {
                const float p = __expf(S[i][j] - mnew);
                S[i][j] = p;
                rsum += p;
            }
            #pragma unroll
            for (int off = 8; off >= 1; off >>= 1)
                rsum += __shfl_xor_sync(0xffffffffu, rsum, off);
            l[i] = l[i] * alpha[i] + rsum;
        }

        // ---- stage P to smem ----
        #pragma unroll
        for (int i = 0; i < 4; i++)
            #pragma unroll
            for (int j = 0; j < 4; j++)
                sP[(ty + 16 * i) * PSTR + (tx + 16 * j)] = S[i][j];
        __syncthreads();

        // ---- O = O*alpha + P @ V : rows ty+16i, col groups 16v + tx ----
        #pragma unroll
        for (int i = 0; i < 4; i++) {
            const float a = alpha[i];
            #pragma unroll
            for (int c = 0; c < 16; c++) Ofrag[i][c] *= a;
        }

        const float4* s4v = (const float4*)sV;
        #pragma unroll 2
        for (int k = 0; k < 64; k++) {
            float p[4];
            #pragma unroll
            for (int i = 0; i < 4; i++) p[i] = sP[(ty + 16 * i) * PSTR + k];
            float4 vv[4];
            #pragma unroll
            for (int v = 0; v < 4; v++) vv[v] = s4v[k * S4 + (16 * v + tx)];
            #pragma unroll
            for (int i = 0; i < 4; i++)
                #pragma unroll
                for (int v = 0; v < 4; v++) {
                    Ofrag[i][4 * v + 0] += p[i] * vv[v].x;
                    Ofrag[i][4 * v + 1] += p[i] * vv[v].y;
                    Ofrag[i][4 * v + 2] += p[i] * vv[v].z;
                    Ofrag[i][4 * v + 3] += p[i] * vv[v].w;
                }
        }
        __syncthreads();
    }

    // ---- finalize: divide by l, store ----
    float4* gO = (float4*)(O + ((size_t)b * N + (size_t)qt * BQ) * DHEAD);
    #pragma unroll
    for (int i = 0; i < 4; i++) {
        const float inv = 1.0f / l[i];
        const int row = ty + 16 * i;
        #pragma unroll
        for (int v = 0; v < 4; v++) {
            float4 o;
            o.x = Ofrag[i][4 * v + 0] * inv;
            o.y = Ofrag[i][4 * v + 1] * inv;
            o.z = Ofrag[i][4 * v + 2] * inv;
            o.w = Ofrag[i][4 * v + 3] * inv;
            gO[row * 64 + (16 * v + tx)] = o;
        }
    }
}

extern "C" void kernel_launch(void* const* d_in, const int* in_sizes, int n_in,
                              void* d_out, int out_size)
{
    const float* Q  = (const float*)d_in[0];
    const float* K  = (const float*)d_in[1];
    const float* V  = (const float*)d_in[2];
    const int*   pm = (const int*)d_in[3];
    float* O = (float*)d_out;

    // Shapes: in_sizes[3] = B*N, in_sizes[0] = B*N*D. N is fixed at 2048.
    const int N = 2048;
    const int BN = in_sizes[3];
    const int B = BN / N;

    // Idempotent, no static guard (kernel_launch must be call-invariant).
    cudaFuncSetAttribute(attn_fa_fp32_kernel,
                         cudaFuncAttributeMaxDynamicSharedMemorySize,
                         SMEM_BYTES);

    dim3 grid(N / BQ, B);
    attn_fa_fp32_kernel<<<grid, 256, SMEM_BYTES>>>(Q, K, V, pm, O, N);
}

// round 6
// speedup vs baseline: 1.8633x; 1.8633x over previous
#include <cuda_runtime.h>
#include <cuda_bf16.h>
#include <stdint.h>
#include <math.h>

#define BATCH 16
#define SEQ   2048
#define DH    256
#define BQ    64
#define BKT   64
#define QSCALE 0.0625f
#define CAPV   20.0f

// bf16 element strides (rows 16B-aligned, odd multiple of 16B -> ldmatrix conflict-free)
#define QSTR 264   // 528 B
#define KSTR 264
#define VSTR 72    // 144 B
#define PSTR 72

// smem byte offsets
#define OFF_PM  0                     // 64 ints
#define OFF_L   256                   // sL[64][2] float
#define OFF_LT  768                   // sLtot[64] float
#define OFF_Q1  1024
#define OFF_Q2  (OFF_Q1 + 64*QSTR*2)  // 34816
#define OFF_K1  (OFF_Q2 + 64*QSTR*2)  // 68608
#define OFF_K2  (OFF_K1 + 64*KSTR*2)  // 102400
#define OFF_V1  (OFF_K2 + 64*KSTR*2)  // 136192
#define OFF_V2  (OFF_V1 + 256*VSTR*2) // 173056
#define OFF_P1  (OFF_V2 + 256*VSTR*2) // 209920
#define OFF_P2  (OFF_P1 + 64*PSTR*2)  // 219136
#define SMEM_TOTAL (OFF_P2 + 64*PSTR*2) // 228352

// ---------------- scratch: bf16 splits, V transposed ----------------
__device__ __nv_bfloat16 g_K1[BATCH * SEQ * DH];
__device__ __nv_bfloat16 g_K2[BATCH * SEQ * DH];
__device__ __nv_bfloat16 g_Vt1[BATCH * DH * SEQ];
__device__ __nv_bfloat16 g_Vt2[BATCH * DH * SEQ];

// ---------------- helpers ----------------
__device__ __forceinline__ uint32_t smem_u32(const void* p) {
    uint32_t a;
    asm("{ .reg .u64 t; cvta.to.shared.u64 t, %1; cvt.u32.u64 %0, t; }" : "=r"(a) : "l"(p));
    return a;
}
__device__ __forceinline__ uint32_t pack2(float lo, float hi) {
    uint32_t r;
    asm("cvt.rn.bf16x2.f32 %0, %1, %2;" : "=r"(r) : "f"(hi), "f"(lo));
    return r;
}
__device__ __forceinline__ void ldsm4(uint32_t r[4], uint32_t addr) {
    asm volatile("ldmatrix.sync.aligned.m8n8.x4.shared.b16 {%0,%1,%2,%3}, [%4];"
                 : "=r"(r[0]), "=r"(r[1]), "=r"(r[2]), "=r"(r[3]) : "r"(addr));
}
__device__ __forceinline__ void mma_bf16(float c[4], const uint32_t a[4], uint32_t b0, uint32_t b1) {
    asm volatile("mma.sync.aligned.m16n8k16.row.col.f32.bf16.bf16.f32 "
                 "{%0,%1,%2,%3}, {%4,%5,%6,%7}, {%8,%9}, {%0,%1,%2,%3};"
                 : "+f"(c[0]), "+f"(c[1]), "+f"(c[2]), "+f"(c[3])
                 : "r"(a[0]), "r"(a[1]), "r"(a[2]), "r"(a[3]), "r"(b0), "r"(b1));
}

// ---------------- pre-pass: K -> bf16 splits ----------------
__global__ void prep_k(const float* __restrict__ K) {
    size_t n4 = (size_t)BATCH * SEQ * DH / 4;
    for (size_t i = (size_t)blockIdx.x * blockDim.x + threadIdx.x; i < n4;
         i += (size_t)gridDim.x * blockDim.x) {
        float4 v = ((const float4*)K)[i];
        __nv_bfloat16 bx = __float2bfloat16_rn(v.x), by = __float2bfloat16_rn(v.y);
        __nv_bfloat16 bz = __float2bfloat16_rn(v.z), bw = __float2bfloat16_rn(v.w);
        uint2 a, b;
        a.x = ((uint32_t)__bfloat16_as_ushort(bx)) | ((uint32_t)__bfloat16_as_ushort(by) << 16);
        a.y = ((uint32_t)__bfloat16_as_ushort(bz)) | ((uint32_t)__bfloat16_as_ushort(bw) << 16);
        b.x = pack2(v.x - __bfloat162float(bx), v.y - __bfloat162float(by));
        b.y = pack2(v.z - __bfloat162float(bz), v.w - __bfloat162float(bw));
        ((uint2*)g_K1)[i] = a;
        ((uint2*)g_K2)[i] = b;
    }
}

// ---------------- pre-pass: V -> transposed bf16 splits ----------------
__global__ void prep_v(const float* __restrict__ V) {
    __shared__ float s[64][65];
    int b = blockIdx.z, n0 = blockIdx.x * 64, d0 = blockIdx.y * 64;
    int t = threadIdx.x;
    #pragma unroll
    for (int i = 0; i < 16; i++) {
        int e = t + 256 * i, ln = e >> 6, ld = e & 63;
        s[ln][ld] = V[((size_t)b * SEQ + n0 + ln) * DH + d0 + ld];
    }
    __syncthreads();
    #pragma unroll
    for (int i = 0; i < 16; i++) {
        int e = t + 256 * i, dd = e >> 6, nn = e & 63;
        float x = s[nn][dd];
        __nv_bfloat16 b1 = __float2bfloat16_rn(x);
        size_t o = ((size_t)b * DH + d0 + dd) * SEQ + n0 + nn;
        g_Vt1[o] = b1;
        g_Vt2[o] = __float2bfloat16_rn(x - __bfloat162float(b1));
    }
}

// ---------------- main kernel: mma.sync bf16-2-split flash attention ----------------
__global__ __launch_bounds__(256, 1)
void attn_mma(const float* __restrict__ Q, const int* __restrict__ pm, float* __restrict__ O)
{
    extern __shared__ char smem[];
    const uint32_t sb = smem_u32(smem);
    const int tid = threadIdx.x, lane = tid & 31, wid = tid >> 5;
    const int wr = wid & 3, wc = wid >> 2;
    const int qt = 31 - blockIdx.x, b = blockIdx.y;
    int* sPm = (int*)(smem + OFF_PM);
    float* sL = (float*)(smem + OFF_L);
    float* sLt = (float*)(smem + OFF_LT);

    const int m0 = 16 * wr;          // S/O row base of this warp
    const int n0 = 32 * wc;          // S col base
    const int g = lane >> 2, t4 = lane & 3;

    // fragment address components (ldmatrix x4 conventions)
    const uint32_t rowA = (uint32_t)(m0 + (lane & 15));
    const uint32_t colA8 = ((lane >> 4) & 1) << 3;
    const uint32_t rowBl = (uint32_t)((lane & 7) + ((lane >> 1) & 8));
    const uint32_t colB8 = (uint32_t)(lane & 8);

    // ---- prologue: load Q tile, scale, split into sQ1/sQ2 ----
    {
        const float4* gQ = (const float4*)(Q + ((size_t)b * SEQ + (size_t)qt * BQ) * DH);
        #pragma unroll
        for (int i = 0; i < 16; i++) {
            int f = tid + 256 * i;          // 0..4095 float4
            int row = f >> 6, c4 = f & 63;  // col in float4 units
            float4 v = gQ[row * 64 + c4];
            v.x *= QSCALE; v.y *= QSCALE; v.z *= QSCALE; v.w *= QSCALE;
            __nv_bfloat16 bx = __float2bfloat16_rn(v.x), by = __float2bfloat16_rn(v.y);
            __nv_bfloat16 bz = __float2bfloat16_rn(v.z), bw = __float2bfloat16_rn(v.w);
            uint2 a1, a2;
            a1.x = ((uint32_t)__bfloat16_as_ushort(bx)) | ((uint32_t)__bfloat16_as_ushort(by) << 16);
            a1.y = ((uint32_t)__bfloat16_as_ushort(bz)) | ((uint32_t)__bfloat16_as_ushort(bw) << 16);
            a2.x = pack2(v.x - __bfloat162float(bx), v.y - __bfloat162float(by));
            a2.y = pack2(v.z - __bfloat162float(bz), v.w - __bfloat162float(bw));
            uint32_t off = (uint32_t)row * (QSTR * 2) + (uint32_t)c4 * 8;
            *(uint2*)(smem + OFF_Q1 + off) = a1;
            *(uint2*)(smem + OFF_Q2 + off) = a2;
        }
    }

    float Oacc[16][4];
    #pragma unroll
    for (int nb = 0; nb < 16; nb++)
        #pragma unroll
        for (int e = 0; e < 4; e++) Oacc[nb][e] = 0.0f;
    float lacc0 = 0.0f, lacc1 = 0.0f;

    for (int j = 0; j <= qt; j++) {
        // ---- load K splits (64 x 256 bf16 each) ----
        {
            const uint4* gk1 = (const uint4*)(g_K1 + ((size_t)b * SEQ + (size_t)j * BKT) * DH);
            const uint4* gk2 = (const uint4*)(g_K2 + ((size_t)b * SEQ + (size_t)j * BKT) * DH);
            #pragma unroll
            for (int i = 0; i < 8; i++) {
                int u = tid + 256 * i;            // 0..2047 uint4
                int row = u >> 5, c16 = u & 31;   // 32 uint4 per row
                uint32_t off = (uint32_t)row * (KSTR * 2) + (uint32_t)c16 * 16;
                *(uint4*)(smem + OFF_K1 + off) = gk1[u];
                *(uint4*)(smem + OFF_K2 + off) = gk2[u];
            }
        }
        // ---- load Vt splits (256 x 64 bf16 each) ----
        {
            const uint4* gv1 = (const uint4*)(g_Vt1 + ((size_t)b * DH + 0) * SEQ + (size_t)j * BKT);
            const uint4* gv2 = (const uint4*)(g_Vt2 + ((size_t)b * DH + 0) * SEQ + (size_t)j * BKT);
            // row = tid (256 rows), 8 uint4 per row; gmem row stride = SEQ bf16 = SEQ/8 uint4
            const uint32_t gstride = SEQ / 8;
            #pragma unroll
            for (int c = 0; c < 8; c++) {
                uint32_t off = (uint32_t)tid * (VSTR * 2) + (uint32_t)c * 16;
                *(uint4*)(smem + OFF_V1 + off) = gv1[(size_t)tid * gstride + c];
                *(uint4*)(smem + OFF_V2 + off) = gv2[(size_t)tid * gstride + c];
            }
        }
        if (tid < BKT) sPm[tid] = pm[(size_t)b * SEQ + (size_t)j * BKT + tid];
        __syncthreads();

        // ---- S = Q1K1 + Q1K2 + Q2K1 (fragments) ----
        float S[4][4];
        #pragma unroll
        for (int nb = 0; nb < 4; nb++)
            #pragma unroll
            for (int e = 0; e < 4; e++) S[nb][e] = 0.0f;

        #pragma unroll 4
        for (int ks = 0; ks < 16; ks++) {
            const uint32_t k0 = ks * 16;
            uint32_t a1[4], a2[4];
            uint32_t aoff = rowA * (QSTR * 2) + (k0 + colA8) * 2;
            ldsm4(a1, sb + OFF_Q1 + aoff);
            ldsm4(a2, sb + OFF_Q2 + aoff);
            #pragma unroll
            for (int np = 0; np < 2; np++) {
                uint32_t b1[4], b2[4];
                uint32_t boff = (uint32_t)(n0 + 16 * np + rowBl) * (KSTR * 2) + (k0 + colB8) * 2;
                ldsm4(b1, sb + OFF_K1 + boff);
                ldsm4(b2, sb + OFF_K2 + boff);
                mma_bf16(S[2 * np], a1, b1[0], b1[1]);
                mma_bf16(S[2 * np], a1, b2[0], b2[1]);
                mma_bf16(S[2 * np], a2, b1[0], b1[1]);
                mma_bf16(S[2 * np + 1], a1, b1[2], b1[3]);
                mma_bf16(S[2 * np + 1], a1, b2[2], b2[3]);
                mma_bf16(S[2 * np + 1], a2, b1[2], b1[3]);
            }
        }

        // ---- mask + exp(s - CAPV) + row sums + split P to smem ----
        const int qg0 = qt * BQ + m0 + g;
        const int qg1 = qg0 + 8;
        const int kb = j * BKT;
        float rs0 = 0.0f, rs1 = 0.0f;
        #pragma unroll
        for (int nb = 0; nb < 4; nb++) {
            const int kl0 = n0 + 8 * nb + 2 * t4;
            const int pm0 = sPm[kl0], pm1 = sPm[kl0 + 1];
            float p00 = ((kb + kl0 <= qg0) && pm0) ? __expf(S[nb][0] - CAPV) : 0.0f;
            float p01 = ((kb + kl0 + 1 <= qg0) && pm1) ? __expf(S[nb][1] - CAPV) : 0.0f;
            float p10 = ((kb + kl0 <= qg1) && pm0) ? __expf(S[nb][2] - CAPV) : 0.0f;
            float p11 = ((kb + kl0 + 1 <= qg1) && pm1) ? __expf(S[nb][3] - CAPV) : 0.0f;
            rs0 += p00 + p01;
            rs1 += p10 + p11;
            __nv_bfloat16 h00 = __float2bfloat16_rn(p00), h01 = __float2bfloat16_rn(p01);
            __nv_bfloat16 h10 = __float2bfloat16_rn(p10), h11 = __float2bfloat16_rn(p11);
            uint32_t w0 = ((uint32_t)__bfloat16_as_ushort(h00)) | ((uint32_t)__bfloat16_as_ushort(h01) << 16);
            uint32_t w1 = ((uint32_t)__bfloat16_as_ushort(h10)) | ((uint32_t)__bfloat16_as_ushort(h11) << 16);
            uint32_t r0 = pack2(p00 - __bfloat162float(h00), p01 - __bfloat162float(h01));
            uint32_t r1 = pack2(p10 - __bfloat162float(h10), p11 - __bfloat162float(h11));
            uint32_t off0 = (uint32_t)(m0 + g) * (PSTR * 2) + (uint32_t)kl0 * 2;
            uint32_t off1 = (uint32_t)(m0 + g + 8) * (PSTR * 2) + (uint32_t)kl0 * 2;
            *(uint32_t*)(smem + OFF_P1 + off0) = w0;
            *(uint32_t*)(smem + OFF_P1 + off1) = w1;
            *(uint32_t*)(smem + OFF_P2 + off0) = r0;
            *(uint32_t*)(smem + OFF_P2 + off1) = r1;
        }
        rs0 += __shfl_xor_sync(0xffffffffu, rs0, 1);
        rs0 += __shfl_xor_sync(0xffffffffu, rs0, 2);
        rs1 += __shfl_xor_sync(0xffffffffu, rs1, 1);
        rs1 += __shfl_xor_sync(0xffffffffu, rs1, 2);
        lacc0 += rs0;
        lacc1 += rs1;
        __syncthreads();

        // ---- O += P1*V1 + P1*V2 + P2*V1 ----
        #pragma unroll
        for (int ks = 0; ks < 4; ks++) {
            const uint32_t k0 = ks * 16;
            uint32_t a1[4], a2[4];
            uint32_t aoff = rowA * (PSTR * 2) + (k0 + colA8) * 2;
            ldsm4(a1, sb + OFF_P1 + aoff);
            ldsm4(a2, sb + OFF_P2 + aoff);
            #pragma unroll
            for (int np = 0; np < 8; np++) {
                uint32_t b1[4], b2[4];
                uint32_t boff = (uint32_t)(128 * wc + 16 * np + rowBl) * (VSTR * 2) + (k0 + colB8) * 2;
                ldsm4(b1, sb + OFF_V1 + boff);
                ldsm4(b2, sb + OFF_V2 + boff);
                mma_bf16(Oacc[2 * np], a1, b1[0], b1[1]);
                mma_bf16(Oacc[2 * np], a1, b2[0], b2[1]);
                mma_bf16(Oacc[2 * np], a2, b1[0], b1[1]);
                mma_bf16(Oacc[2 * np + 1], a1, b1[2], b1[3]);
                mma_bf16(Oacc[2 * np + 1], a1, b2[2], b2[3]);
                mma_bf16(Oacc[2 * np + 1], a2, b1[2], b1[3]);
            }
        }
        __syncthreads();
    }

    // ---- combine l across the two col-half warps, then store O / l ----
    if (t4 == 0) {
        sL[(m0 + g) * 2 + wc] = lacc0;
        sL[(m0 + g + 8) * 2 + wc] = lacc1;
    }
    __syncthreads();
    if (tid < 64) sLt[tid] = sL[tid * 2] + sL[tid * 2 + 1];
    __syncthreads();

    const float linv0 = 1.0f / sLt[m0 + g];
    const float linv1 = 1.0f / sLt[m0 + g + 8];
    float* gO = O + ((size_t)b * SEQ + (size_t)qt * BQ) * DH;
    const int row0 = m0 + g, row1 = m0 + g + 8;
    #pragma unroll
    for (int nb = 0; nb < 16; nb++) {
        const int col = 128 * wc + 8 * nb + 2 * t4;
        float2 v0 = make_float2(Oacc[nb][0] * linv0, Oacc[nb][1] * linv0);
        float2 v1 = make_float2(Oacc[nb][2] * linv1, Oacc[nb][3] * linv1);
        *(float2*)(gO + (size_t)row0 * DH + col) = v0;
        *(float2*)(gO + (size_t)row1 * DH + col) = v1;
    }
}

// ---------------- launch ----------------
extern "C" void kernel_launch(void* const* d_in, const int* in_sizes, int n_in,
                              void* d_out, int out_size)
{
    const float* Q  = (const float*)d_in[0];
    const float* K  = (const float*)d_in[1];
    const float* V  = (const float*)d_in[2];
    const int*   pm = (const int*)d_in[3];
    float* O = (float*)d_out;

    prep_k<<<2048, 256>>>(K);
    prep_v<<<dim3(SEQ / 64, DH / 64, BATCH), 256>>>(V);

    cudaFuncSetAttribute(attn_mma, cudaFuncAttributeMaxDynamicSharedMemorySize, SMEM_TOTAL);
    attn_mma<<<dim3(SEQ / BQ, BATCH), 256, SMEM_TOTAL>>>(Q, pm, O);
}

// round 7
// speedup vs baseline: 2.1614x; 1.1600x over previous
#include <cuda_runtime.h>
#include <cuda_bf16.h>
#include <stdint.h>
#include <math.h>

#define BATCH 16
#define SEQ   2048
#define DH    256
#define BQ    64
#define BKT   64
#define QSCALE 0.0625f
#define CAPV   20.0f

// bf16 element strides (rows 16B-aligned, odd multiple of 16B -> ldmatrix conflict-free)
#define QSTR 264   // 528 B
#define KSTR 264
#define VSTR 72    // 144 B
#define PSTR 72

// smem byte offsets
#define OFF_PM  0                     // 64 ints
#define OFF_L   256                   // sL[64][2] float
#define OFF_LT  768                   // sLtot[64] float
#define OFF_Q1  1024
#define OFF_Q2  (OFF_Q1 + 64*QSTR*2)  // 34816
#define OFF_K1  (OFF_Q2 + 64*QSTR*2)  // 68608
#define OFF_K2  (OFF_K1 + 64*KSTR*2)  // 102400
#define OFF_V1  (OFF_K2 + 64*KSTR*2)  // 136192
#define OFF_V2  (OFF_V1 + 256*VSTR*2) // 173056
#define OFF_P1  (OFF_V2 + 256*VSTR*2) // 209920
#define OFF_P2  (OFF_P1 + 64*PSTR*2)  // 219136
#define SMEM_TOTAL (OFF_P2 + 64*PSTR*2) // 228352

// ---------------- scratch: bf16 splits, V transposed ----------------
__device__ __nv_bfloat16 g_K1[BATCH * SEQ * DH];
__device__ __nv_bfloat16 g_K2[BATCH * SEQ * DH];
__device__ __nv_bfloat16 g_Vt1[BATCH * DH * SEQ];
__device__ __nv_bfloat16 g_Vt2[BATCH * DH * SEQ];

// ---------------- helpers ----------------
__device__ __forceinline__ uint32_t smem_u32(const void* p) {
    uint32_t a;
    asm("{ .reg .u64 t; cvta.to.shared.u64 t, %1; cvt.u32.u64 %0, t; }" : "=r"(a) : "l"(p));
    return a;
}
__device__ __forceinline__ uint32_t pack2(float lo, float hi) {
    uint32_t r;
    asm("cvt.rn.bf16x2.f32 %0, %1, %2;" : "=r"(r) : "f"(hi), "f"(lo));
    return r;
}
__device__ __forceinline__ void ldsm4(uint32_t r[4], uint32_t addr) {
    asm volatile("ldmatrix.sync.aligned.m8n8.x4.shared.b16 {%0,%1,%2,%3}, [%4];"
                 : "=r"(r[0]), "=r"(r[1]), "=r"(r[2]), "=r"(r[3]) : "r"(addr));
}
__device__ __forceinline__ void mma_bf16(float c[4], const uint32_t a[4], uint32_t b0, uint32_t b1) {
    asm volatile("mma.sync.aligned.m16n8k16.row.col.f32.bf16.bf16.f32 "
                 "{%0,%1,%2,%3}, {%4,%5,%6,%7}, {%8,%9}, {%0,%1,%2,%3};"
                 : "+f"(c[0]), "+f"(c[1]), "+f"(c[2]), "+f"(c[3])
                 : "r"(a[0]), "r"(a[1]), "r"(a[2]), "r"(a[3]), "r"(b0), "r"(b1));
}

// ---------------- pre-pass: K -> bf16 splits ----------------
__global__ void prep_k(const float* __restrict__ K) {
    size_t n4 = (size_t)BATCH * SEQ * DH / 4;
    for (size_t i = (size_t)blockIdx.x * blockDim.x + threadIdx.x; i < n4;
         i += (size_t)gridDim.x * blockDim.x) {
        float4 v = ((const float4*)K)[i];
        __nv_bfloat16 bx = __float2bfloat16_rn(v.x), by = __float2bfloat16_rn(v.y);
        __nv_bfloat16 bz = __float2bfloat16_rn(v.z), bw = __float2bfloat16_rn(v.w);
        uint2 a, b;
        a.x = ((uint32_t)__bfloat16_as_ushort(bx)) | ((uint32_t)__bfloat16_as_ushort(by) << 16);
        a.y = ((uint32_t)__bfloat16_as_ushort(bz)) | ((uint32_t)__bfloat16_as_ushort(bw) << 16);
        b.x = pack2(v.x - __bfloat162float(bx), v.y - __bfloat162float(by));
        b.y = pack2(v.z - __bfloat162float(bz), v.w - __bfloat162float(bw));
        ((uint2*)g_K1)[i] = a;
        ((uint2*)g_K2)[i] = b;
    }
}

// ---------------- pre-pass: V -> transposed bf16 splits ----------------
__global__ void prep_v(const float* __restrict__ V) {
    __shared__ float s[64][65];
    int b = blockIdx.z, n0 = blockIdx.x * 64, d0 = blockIdx.y * 64;
    int t = threadIdx.x;
    #pragma unroll
    for (int i = 0; i < 16; i++) {
        int e = t + 256 * i, ln = e >> 6, ld = e & 63;
        s[ln][ld] = V[((size_t)b * SEQ + n0 + ln) * DH + d0 + ld];
    }
    __syncthreads();
    #pragma unroll
    for (int i = 0; i < 16; i++) {
        int e = t + 256 * i, dd = e >> 6, nn = e & 63;
        float x = s[nn][dd];
        __nv_bfloat16 b1 = __float2bfloat16_rn(x);
        size_t o = ((size_t)b * DH + d0 + dd) * SEQ + n0 + nn;
        g_Vt1[o] = b1;
        g_Vt2[o] = __float2bfloat16_rn(x - __bfloat162float(b1));
    }
}

// ---------------- main kernel: mma.sync bf16-2-split flash attention ----------------
__global__ __launch_bounds__(256, 1)
void attn_mma(const float* __restrict__ Q, const int* __restrict__ pm, float* __restrict__ O)
{
    extern __shared__ char smem[];
    const uint32_t sb = smem_u32(smem);
    const int tid = threadIdx.x, lane = tid & 31, wid = tid >> 5;
    const int wr = wid & 3, wc = wid >> 2;
    const int qt = 31 - blockIdx.x, b = blockIdx.y;
    int* sPm = (int*)(smem + OFF_PM);
    float* sL = (float*)(smem + OFF_L);
    float* sLt = (float*)(smem + OFF_LT);

    const int m0 = 16 * wr;          // S/O row base of this warp
    const int n0 = 32 * wc;          // S col base
    const int g = lane >> 2, t4 = lane & 3;

    // fragment address components (ldmatrix x4 conventions)
    const uint32_t rowA = (uint32_t)(m0 + (lane & 15));
    const uint32_t colA8 = ((lane >> 4) & 1) << 3;
    const uint32_t rowBl = (uint32_t)((lane & 7) + ((lane >> 1) & 8));
    const uint32_t colB8 = (uint32_t)(lane & 8);

    // global pointers for the K/V prefetch (per-thread fixed lanes)
    const uint4* gk1b = (const uint4*)(g_K1 + (size_t)b * SEQ * DH);
    const uint4* gk2b = (const uint4*)(g_K2 + (size_t)b * SEQ * DH);
    const uint4* gv1b = (const uint4*)(g_Vt1 + (size_t)b * DH * SEQ);
    const uint4* gv2b = (const uint4*)(g_Vt2 + (size_t)b * DH * SEQ);
    const uint32_t vgstride = SEQ / 8;  // uint4 per Vt row

    // ---- prologue: load Q tile, scale, split into sQ1/sQ2 ----
    {
        const float4* gQ = (const float4*)(Q + ((size_t)b * SEQ + (size_t)qt * BQ) * DH);
        #pragma unroll
        for (int i = 0; i < 16; i++) {
            int f = tid + 256 * i;          // 0..4095 float4
            int row = f >> 6, c4 = f & 63;
            float4 v = gQ[row * 64 + c4];
            v.x *= QSCALE; v.y *= QSCALE; v.z *= QSCALE; v.w *= QSCALE;
            __nv_bfloat16 bx = __float2bfloat16_rn(v.x), by = __float2bfloat16_rn(v.y);
            __nv_bfloat16 bz = __float2bfloat16_rn(v.z), bw = __float2bfloat16_rn(v.w);
            uint2 a1, a2;
            a1.x = ((uint32_t)__bfloat16_as_ushort(bx)) | ((uint32_t)__bfloat16_as_ushort(by) << 16);
            a1.y = ((uint32_t)__bfloat16_as_ushort(bz)) | ((uint32_t)__bfloat16_as_ushort(bw) << 16);
            a2.x = pack2(v.x - __bfloat162float(bx), v.y - __bfloat162float(by));
            a2.y = pack2(v.z - __bfloat162float(bz), v.w - __bfloat162float(bw));
            uint32_t off = (uint32_t)row * (QSTR * 2) + (uint32_t)c4 * 8;
            *(uint2*)(smem + OFF_Q1 + off) = a1;
            *(uint2*)(smem + OFF_Q2 + off) = a2;
        }
    }

    float Oacc[16][4];
    #pragma unroll
    for (int nb = 0; nb < 16; nb++)
        #pragma unroll
        for (int e = 0; e < 4; e++) Oacc[nb][e] = 0.0f;
    float lacc0 = 0.0f, lacc1 = 0.0f;

    // ---- preload K tile j=0 into registers ----
    uint4 kreg1[8], kreg2[8];
    {
        const uint4* gk1 = gk1b;  // j = 0
        const uint4* gk2 = gk2b;
        #pragma unroll
        for (int i = 0; i < 8; i++) {
            int u = tid + 256 * i;
            kreg1[i] = gk1[u];
            kreg2[i] = gk2[u];
        }
    }

    for (int j = 0; j <= qt; j++) {
        // ---- store K tile j from registers into smem ----
        #pragma unroll
        for (int i = 0; i < 8; i++) {
            int u = tid + 256 * i;            // 0..2047 uint4
            int row = u >> 5, c16 = u & 31;
            uint32_t off = (uint32_t)row * (KSTR * 2) + (uint32_t)c16 * 16;
            *(uint4*)(smem + OFF_K1 + off) = kreg1[i];
            *(uint4*)(smem + OFF_K2 + off) = kreg2[i];
        }
        // ---- issue LDG for V tile j (consumed after S compute) ----
        uint4 vreg1[8], vreg2[8];
        {
            const uint4* gv1 = gv1b + (size_t)j * (BKT / 8);
            const uint4* gv2 = gv2b + (size_t)j * (BKT / 8);
            #pragma unroll
            for (int c = 0; c < 8; c++) {
                vreg1[c] = gv1[(size_t)tid * vgstride + c];
                vreg2[c] = gv2[(size_t)tid * vgstride + c];
            }
        }
        if (tid < BKT) sPm[tid] = pm[(size_t)b * SEQ + (size_t)j * BKT + tid];
        __syncthreads();   // sync1: sK_j + sPm visible; all threads past PV_{j-1}

        // ---- S = Q1K1 + Q1K2 + Q2K1 (fragments) ----
        float S[4][4];
        #pragma unroll
        for (int nb = 0; nb < 4; nb++)
            #pragma unroll
            for (int e = 0; e < 4; e++) S[nb][e] = 0.0f;

        #pragma unroll 4
        for (int ks = 0; ks < 16; ks++) {
            const uint32_t k0 = ks * 16;
            uint32_t a1[4], a2[4];
            uint32_t aoff = rowA * (QSTR * 2) + (k0 + colA8) * 2;
            ldsm4(a1, sb + OFF_Q1 + aoff);
            ldsm4(a2, sb + OFF_Q2 + aoff);
            #pragma unroll
            for (int np = 0; np < 2; np++) {
                uint32_t b1[4], b2[4];
                uint32_t boff = (uint32_t)(n0 + 16 * np + rowBl) * (KSTR * 2) + (k0 + colB8) * 2;
                ldsm4(b1, sb + OFF_K1 + boff);
                ldsm4(b2, sb + OFF_K2 + boff);
                mma_bf16(S[2 * np], a1, b1[0], b1[1]);
                mma_bf16(S[2 * np], a1, b2[0], b2[1]);
                mma_bf16(S[2 * np], a2, b1[0], b1[1]);
                mma_bf16(S[2 * np + 1], a1, b1[2], b1[3]);
                mma_bf16(S[2 * np + 1], a1, b2[2], b2[3]);
                mma_bf16(S[2 * np + 1], a2, b1[2], b1[3]);
            }
        }

        // ---- mask + exp(s - CAPV) + row sums + split P to smem ----
        const int qg0 = qt * BQ + m0 + g;
        const int qg1 = qg0 + 8;
        const int kb = j * BKT;
        float rs0 = 0.0f, rs1 = 0.0f;
        #pragma unroll
        for (int nb = 0; nb < 4; nb++) {
            const int kl0 = n0 + 8 * nb + 2 * t4;
            const int pm0 = sPm[kl0], pm1 = sPm[kl0 + 1];
            float p00 = ((kb + kl0 <= qg0) && pm0) ? __expf(S[nb][0] - CAPV) : 0.0f;
            float p01 = ((kb + kl0 + 1 <= qg0) && pm1) ? __expf(S[nb][1] - CAPV) : 0.0f;
            float p10 = ((kb + kl0 <= qg1) && pm0) ? __expf(S[nb][2] - CAPV) : 0.0f;
            float p11 = ((kb + kl0 + 1 <= qg1) && pm1) ? __expf(S[nb][3] - CAPV) : 0.0f;
            rs0 += p00 + p01;
            rs1 += p10 + p11;
            __nv_bfloat16 h00 = __float2bfloat16_rn(p00), h01 = __float2bfloat16_rn(p01);
            __nv_bfloat16 h10 = __float2bfloat16_rn(p10), h11 = __float2bfloat16_rn(p11);
            uint32_t w0 = ((uint32_t)__bfloat16_as_ushort(h00)) | ((uint32_t)__bfloat16_as_ushort(h01) << 16);
            uint32_t w1 = ((uint32_t)__bfloat16_as_ushort(h10)) | ((uint32_t)__bfloat16_as_ushort(h11) << 16);
            uint32_t r0 = pack2(p00 - __bfloat162float(h00), p01 - __bfloat162float(h01));
            uint32_t r1 = pack2(p10 - __bfloat162float(h10), p11 - __bfloat162float(h11));
            uint32_t off0 = (uint32_t)(m0 + g) * (PSTR * 2) + (uint32_t)kl0 * 2;
            uint32_t off1 = (uint32_t)(m0 + g + 8) * (PSTR * 2) + (uint32_t)kl0 * 2;
            *(uint32_t*)(smem + OFF_P1 + off0) = w0;
            *(uint32_t*)(smem + OFF_P1 + off1) = w1;
            *(uint32_t*)(smem + OFF_P2 + off0) = r0;
            *(uint32_t*)(smem + OFF_P2 + off1) = r1;
        }
        rs0 += __shfl_xor_sync(0xffffffffu, rs0, 1);
        rs0 += __shfl_xor_sync(0xffffffffu, rs0, 2);
        rs1 += __shfl_xor_sync(0xffffffffu, rs1, 1);
        rs1 += __shfl_xor_sync(0xffffffffu, rs1, 2);
        lacc0 += rs0;
        lacc1 += rs1;

        // ---- store V tile j from registers (LDG issued ~S-phase ago) ----
        #pragma unroll
        for (int c = 0; c < 8; c++) {
            uint32_t off = (uint32_t)tid * (VSTR * 2) + (uint32_t)c * 16;
            *(uint4*)(smem + OFF_V1 + off) = vreg1[c];
            *(uint4*)(smem + OFF_V2 + off) = vreg2[c];
        }
        __syncthreads();   // sync2: sP_j + sV_j visible

        // ---- issue LDG for K tile j+1 (hidden under PV compute) ----
        if (j < qt) {
            const uint4* gk1 = gk1b + (size_t)(j + 1) * BKT * (DH / 8);
            const uint4* gk2 = gk2b + (size_t)(j + 1) * BKT * (DH / 8);
            #pragma unroll
            for (int i = 0; i < 8; i++) {
                int u = tid + 256 * i;
                kreg1[i] = gk1[u];
                kreg2[i] = gk2[u];
            }
        }

        // ---- O += P1*V1 + P1*V2 + P2*V1 ----
        #pragma unroll
        for (int ks = 0; ks < 4; ks++) {
            const uint32_t k0 = ks * 16;
            uint32_t a1[4], a2[4];
            uint32_t aoff = rowA * (PSTR * 2) + (k0 + colA8) * 2;
            ldsm4(a1, sb + OFF_P1 + aoff);
            ldsm4(a2, sb + OFF_P2 + aoff);
            #pragma unroll
            for (int np = 0; np < 8; np++) {
                uint32_t b1[4], b2[4];
                uint32_t boff = (uint32_t)(128 * wc + 16 * np + rowBl) * (VSTR * 2) + (k0 + colB8) * 2;
                ldsm4(b1, sb + OFF_V1 + boff);
                ldsm4(b2, sb + OFF_V2 + boff);
                mma_bf16(Oacc[2 * np], a1, b1[0], b1[1]);
                mma_bf16(Oacc[2 * np], a1, b2[0], b2[1]);
                mma_bf16(Oacc[2 * np], a2, b1[0], b1[1]);
                mma_bf16(Oacc[2 * np + 1], a1, b1[2], b1[3]);
                mma_bf16(Oacc[2 * np + 1], a1, b2[2], b2[3]);
                mma_bf16(Oacc[2 * np + 1], a2, b1[2], b1[3]);
            }
        }
    }

    // ---- combine l across the two col-half warps, then store O / l ----
    __syncthreads();
    if (t4 == 0) {
        sL[(m0 + g) * 2 + wc] = lacc0;
        sL[(m0 + g + 8) * 2 + wc] = lacc1;
    }
    __syncthreads();
    if (tid < 64) sLt[tid] = sL[tid * 2] + sL[tid * 2 + 1];
    __syncthreads();

    const float linv0 = 1.0f / sLt[m0 + g];
    const float linv1 = 1.0f / sLt[m0 + g + 8];
    float* gO = O + ((size_t)b * SEQ + (size_t)qt * BQ) * DH;
    const int row0 = m0 + g, row1 = m0 + g + 8;
    #pragma unroll
    for (int nb = 0; nb < 16; nb++) {
        const int col = 128 * wc + 8 * nb + 2 * t4;
        float2 v0 = make_float2(Oacc[nb][0] * linv0, Oacc[nb][1] * linv0);
        float2 v1 = make_float2(Oacc[nb][2] * linv1, Oacc[nb][3] * linv1);
        *(float2*)(gO + (size_t)row0 * DH + col) = v0;
        *(float2*)(gO + (size_t)row1 * DH + col) = v1;
    }
}

// ---------------- launch ----------------
extern "C" void kernel_launch(void* const* d_in, const int* in_sizes, int n_in,
                              void* d_out, int out_size)
{
    const float* Q  = (const float*)d_in[0];
    const float* K  = (const float*)d_in[1];
    const float* V  = (const float*)d_in[2];
    const int*   pm = (const int*)d_in[3];
    float* O = (float*)d_out;

    prep_k<<<2048, 256>>>(K);
    prep_v<<<dim3(SEQ / 64, DH / 64, BATCH), 256>>>(V);

    cudaFuncSetAttribute(attn_mma, cudaFuncAttributeMaxDynamicSharedMemorySize, SMEM_TOTAL);
    attn_mma<<<dim3(SEQ / BQ, BATCH), 256, SMEM_TOTAL>>>(Q, pm, O);
}

// round 8
// speedup vs baseline: 2.6447x; 1.2236x over previous
#include <cuda_runtime.h>
#include <cuda_bf16.h>
#include <stdint.h>
#include <math.h>

#define BATCH 16
#define SEQ   2048
#define DH    256
#define BQ    64
#define BKT   64
#define QSCALE 0.0625f
#define CAPV   20.0f

// bf16 element strides (rows 16B-aligned, odd multiple of 16B -> conflict-free ldsm)
#define QSTR 264   // 528 B rows
#define KSTR 264
#define VSTR 72    // 144 B rows
#define PSTR 72

// smem byte offsets
#define OFF_PM  0                     // 64 ints (256B)
#define OFF_L   256                   // sL[64][4] float (1024B)
#define OFF_LT  1280                  // sLtot[64] float (256B)
#define OFF_Q1  2048
#define OFF_Q2  (OFF_Q1 + 64*QSTR*2)  // +33792
#define OFF_K1  (OFF_Q2 + 64*QSTR*2)
#define OFF_K2  (OFF_K1 + 64*KSTR*2)
#define OFF_V1  (OFF_K2 + 64*KSTR*2)
#define OFF_V2  (OFF_V1 + 256*VSTR*2) // +36864
#define OFF_P1  (OFF_V2 + 256*VSTR*2)
#define OFF_P2  (OFF_P1 + 64*PSTR*2)  // +9216
#define SMEM_TOTAL (OFF_P2 + 64*PSTR*2)  // 229376

// ---------------- scratch: bf16 splits, V transposed ----------------
__device__ __nv_bfloat16 g_K1[BATCH * SEQ * DH];
__device__ __nv_bfloat16 g_K2[BATCH * SEQ * DH];
__device__ __nv_bfloat16 g_Vt1[BATCH * DH * SEQ];
__device__ __nv_bfloat16 g_Vt2[BATCH * DH * SEQ];

// ---------------- helpers ----------------
__device__ __forceinline__ uint32_t smem_u32(const void* p) {
    uint32_t a;
    asm("{ .reg .u64 t; cvta.to.shared.u64 t, %1; cvt.u32.u64 %0, t; }" : "=r"(a) : "l"(p));
    return a;
}
__device__ __forceinline__ uint32_t pack2(float lo, float hi) {
    uint32_t r;
    asm("cvt.rn.bf16x2.f32 %0, %1, %2;" : "=r"(r) : "f"(hi), "f"(lo));
    return r;
}
__device__ __forceinline__ void ldsm4(uint32_t r[4], uint32_t addr) {
    asm volatile("ldmatrix.sync.aligned.m8n8.x4.shared.b16 {%0,%1,%2,%3}, [%4];"
                 : "=r"(r[0]), "=r"(r[1]), "=r"(r[2]), "=r"(r[3]) : "r"(addr));
}
__device__ __forceinline__ void mma_bf16(float c[4], const uint32_t a[4], uint32_t b0, uint32_t b1) {
    asm volatile("mma.sync.aligned.m16n8k16.row.col.f32.bf16.bf16.f32 "
                 "{%0,%1,%2,%3}, {%4,%5,%6,%7}, {%8,%9}, {%0,%1,%2,%3};"
                 : "+f"(c[0]), "+f"(c[1]), "+f"(c[2]), "+f"(c[3])
                 : "r"(a[0]), "r"(a[1]), "r"(a[2]), "r"(a[3]), "r"(b0), "r"(b1));
}
__device__ __forceinline__ void cpasync16(uint32_t saddr, const void* gaddr) {
    asm volatile("cp.async.cg.shared.global [%0], [%1], 16;" :: "r"(saddr), "l"(gaddr));
}
#define CP_COMMIT() asm volatile("cp.async.commit_group;" ::: "memory")
#define CP_WAIT0()  asm volatile("cp.async.wait_group 0;" ::: "memory")

// ---------------- merged pre-pass: K splits + V transposed splits ----------------
// grid (32, 4, 16), block 256
__global__ void prep(const float* __restrict__ K, const float* __restrict__ V) {
    const int t = threadIdx.x;
    // --- K part: this block's linear share of 2,097,152 float4 ---
    {
        const size_t blk = blockIdx.x + 32 * blockIdx.y + 128 * (size_t)blockIdx.z; // 0..2047
        const float4* k4 = (const float4*)K;
        #pragma unroll
        for (int u = 0; u < 4; u++) {
            size_t i = blk * 1024 + t + 256 * u;
            float4 v = k4[i];
            __nv_bfloat16 bx = __float2bfloat16_rn(v.x), by = __float2bfloat16_rn(v.y);
            __nv_bfloat16 bz = __float2bfloat16_rn(v.z), bw = __float2bfloat16_rn(v.w);
            uint2 a, b;
            a.x = ((uint32_t)__bfloat16_as_ushort(bx)) | ((uint32_t)__bfloat16_as_ushort(by) << 16);
            a.y = ((uint32_t)__bfloat16_as_ushort(bz)) | ((uint32_t)__bfloat16_as_ushort(bw) << 16);
            b.x = pack2(v.x - __bfloat162float(bx), v.y - __bfloat162float(by));
            b.y = pack2(v.z - __bfloat162float(bz), v.w - __bfloat162float(bw));
            ((uint2*)g_K1)[i] = a;
            ((uint2*)g_K2)[i] = b;
        }
    }
    // --- V part: transpose 64x64 tile (b=z, n0=64x, d0=64y) ---
    __shared__ float s[64][65];
    const int b = blockIdx.z, n0 = blockIdx.x * 64, d0 = blockIdx.y * 64;
    #pragma unroll
    for (int i = 0; i < 16; i++) {
        int e = t + 256 * i, ln = e >> 6, ld = e & 63;
        s[ln][ld] = V[((size_t)b * SEQ + n0 + ln) * DH + d0 + ld];
    }
    __syncthreads();
    #pragma unroll
    for (int i = 0; i < 16; i++) {
        int e = t + 256 * i, dd = e >> 6, nn = e & 63;
        float x = s[nn][dd];
        __nv_bfloat16 b1 = __float2bfloat16_rn(x);
        size_t o = ((size_t)b * DH + d0 + dd) * SEQ + n0 + nn;
        g_Vt1[o] = b1;
        g_Vt2[o] = __float2bfloat16_rn(x - __bfloat162float(b1));
    }
}

// ---------------- main kernel: 16-warp mma.sync bf16-2-split flash attention ----------------
__global__ __launch_bounds__(512, 1)
void attn_mma(const float* __restrict__ Q, const int* __restrict__ pm, float* __restrict__ O)
{
    extern __shared__ char smem[];
    const uint32_t sb = smem_u32(smem);
    const int tid = threadIdx.x, lane = tid & 31, wid = tid >> 5;
    const int wr = wid & 3, wc = wid >> 2;          // 4 x 4 warp grid
    const int qt = 31 - blockIdx.x, b = blockIdx.y;
    int* sPm = (int*)(smem + OFF_PM);
    float* sL = (float*)(smem + OFF_L);
    float* sLt = (float*)(smem + OFF_LT);

    const int m0 = 16 * wr;           // S/O row base
    const int nS = 16 * wc;           // S col base (16 cols per warp)
    const int nO = 64 * wc;           // O col base (64 cols per warp)
    const int g = lane >> 2, t4 = lane & 3;

    // ldmatrix x4 lane-address components
    const uint32_t rowA = (uint32_t)(m0 + (lane & 15));
    const uint32_t colA8 = ((lane >> 4) & 1) << 3;
    const uint32_t rowBl = (uint32_t)((lane & 7) + ((lane >> 1) & 8));
    const uint32_t colB8 = (uint32_t)(lane & 8);

    const uint4* gk1b = (const uint4*)(g_K1 + (size_t)b * SEQ * DH);
    const uint4* gk2b = (const uint4*)(g_K2 + (size_t)b * SEQ * DH);
    const uint4* gv1b = (const uint4*)(g_Vt1 + (size_t)b * DH * SEQ);
    const uint4* gv2b = (const uint4*)(g_Vt2 + (size_t)b * DH * SEQ);

    // ---- prologue: load Q tile, scale, split into sQ1/sQ2 ----
    {
        const float4* gQ = (const float4*)(Q + ((size_t)b * SEQ + (size_t)qt * BQ) * DH);
        #pragma unroll
        for (int i = 0; i < 8; i++) {
            int f = tid + 512 * i;          // 0..4095 float4
            int row = f >> 6, c4 = f & 63;
            float4 v = gQ[row * 64 + c4];
            v.x *= QSCALE; v.y *= QSCALE; v.z *= QSCALE; v.w *= QSCALE;
            __nv_bfloat16 bx = __float2bfloat16_rn(v.x), by = __float2bfloat16_rn(v.y);
            __nv_bfloat16 bz = __float2bfloat16_rn(v.z), bw = __float2bfloat16_rn(v.w);
            uint2 a1, a2;
            a1.x = ((uint32_t)__bfloat16_as_ushort(bx)) | ((uint32_t)__bfloat16_as_ushort(by) << 16);
            a1.y = ((uint32_t)__bfloat16_as_ushort(bz)) | ((uint32_t)__bfloat16_as_ushort(bw) << 16);
            a2.x = pack2(v.x - __bfloat162float(bx), v.y - __bfloat162float(by));
            a2.y = pack2(v.z - __bfloat162float(bz), v.w - __bfloat162float(bw));
            uint32_t off = (uint32_t)row * (QSTR * 2) + (uint32_t)c4 * 8;
            *(uint2*)(smem + OFF_Q1 + off) = a1;
            *(uint2*)(smem + OFF_Q2 + off) = a2;
        }
    }

    // ---- preload K tile j=0 via cp.async ----
    {
        #pragma unroll
        for (int i = 0; i < 4; i++) {
            int u = tid + 512 * i;            // 0..2047 uint4
            int row = u >> 5, c16 = u & 31;
            uint32_t off = (uint32_t)row * (KSTR * 2) + (uint32_t)c16 * 16;
            cpasync16(sb + OFF_K1 + off, gk1b + u);
            cpasync16(sb + OFF_K2 + off, gk2b + u);
        }
        CP_COMMIT();
    }

    float Oacc[8][4];
    #pragma unroll
    for (int nb = 0; nb < 8; nb++)
        #pragma unroll
        for (int e = 0; e < 4; e++) Oacc[nb][e] = 0.0f;
    float lacc0 = 0.0f, lacc1 = 0.0f;

    for (int j = 0; j <= qt; j++) {
        CP_WAIT0();   // K tile j landed
        if (tid < BKT) sPm[tid] = pm[(size_t)b * SEQ + (size_t)j * BKT + tid];
        __syncthreads();   // sync1: sK_j + sPm visible; all warps done with sV_{j-1}

        // ---- issue cp.async for V tile j (waited after S-phase) ----
        {
            #pragma unroll
            for (int i = 0; i < 4; i++) {
                int u = tid + 512 * i;        // 0..2047 uint4 (256 rows x 8)
                int d = u >> 3, c = u & 7;
                uint32_t off = (uint32_t)d * (VSTR * 2) + (uint32_t)c * 16;
                const uint4* gv1 = gv1b + (size_t)j * (BKT / 8) + (size_t)d * (SEQ / 8) + c;
                const uint4* gv2 = gv2b + (size_t)j * (BKT / 8) + (size_t)d * (SEQ / 8) + c;
                cpasync16(sb + OFF_V1 + off, gv1);
                cpasync16(sb + OFF_V2 + off, gv2);
            }
            CP_COMMIT();
        }

        // ---- S = Q1K1 + Q1K2 + Q2K1, 3 separate accumulator sets ----
        float Sa[2][4], Sb[2][4], Sc[2][4];
        #pragma unroll
        for (int nb = 0; nb < 2; nb++)
            #pragma unroll
            for (int e = 0; e < 4; e++) { Sa[nb][e] = 0.0f; Sb[nb][e] = 0.0f; Sc[nb][e] = 0.0f; }

        #pragma unroll 4
        for (int ks = 0; ks < 16; ks++) {
            const uint32_t k0 = ks * 16;
            uint32_t a1[4], a2[4], b1[4], b2[4];
            uint32_t aoff = rowA * (QSTR * 2) + (k0 + colA8) * 2;
            uint32_t boff = (uint32_t)(nS + rowBl) * (KSTR * 2) + (k0 + colB8) * 2;
            ldsm4(a1, sb + OFF_Q1 + aoff);
            ldsm4(a2, sb + OFF_Q2 + aoff);
            ldsm4(b1, sb + OFF_K1 + boff);
            ldsm4(b2, sb + OFF_K2 + boff);
            mma_bf16(Sa[0], a1, b1[0], b1[1]);
            mma_bf16(Sb[0], a1, b2[0], b2[1]);
            mma_bf16(Sc[0], a2, b1[0], b1[1]);
            mma_bf16(Sa[1], a1, b1[2], b1[3]);
            mma_bf16(Sb[1], a1, b2[2], b2[3]);
            mma_bf16(Sc[1], a2, b1[2], b1[3]);
        }

        CP_WAIT0();   // V tile j landed (S-phase hid the latency)

        // ---- mask + exp(s-CAPV) + row sums + split P to smem ----
        const int qg0 = qt * BQ + m0 + g;
        const int qg1 = qg0 + 8;
        const int kb = j * BKT;
        float rs0 = 0.0f, rs1 = 0.0f;
        #pragma unroll
        for (int nb = 0; nb < 2; nb++) {
            const int kl0 = nS + 8 * nb + 2 * t4;
            const int pm0 = sPm[kl0], pm1 = sPm[kl0 + 1];
            float s00 = Sa[nb][0] + Sb[nb][0] + Sc[nb][0];
            float s01 = Sa[nb][1] + Sb[nb][1] + Sc[nb][1];
            float s10 = Sa[nb][2] + Sb[nb][2] + Sc[nb][2];
            float s11 = Sa[nb][3] + Sb[nb][3] + Sc[nb][3];
            float p00 = ((kb + kl0 <= qg0) && pm0) ? __expf(s00 - CAPV) : 0.0f;
            float p01 = ((kb + kl0 + 1 <= qg0) && pm1) ? __expf(s01 - CAPV) : 0.0f;
            float p10 = ((kb + kl0 <= qg1) && pm0) ? __expf(s10 - CAPV) : 0.0f;
            float p11 = ((kb + kl0 + 1 <= qg1) && pm1) ? __expf(s11 - CAPV) : 0.0f;
            rs0 += p00 + p01;
            rs1 += p10 + p11;
            __nv_bfloat16 h00 = __float2bfloat16_rn(p00), h01 = __float2bfloat16_rn(p01);
            __nv_bfloat16 h10 = __float2bfloat16_rn(p10), h11 = __float2bfloat16_rn(p11);
            uint32_t w0 = ((uint32_t)__bfloat16_as_ushort(h00)) | ((uint32_t)__bfloat16_as_ushort(h01) << 16);
            uint32_t w1 = ((uint32_t)__bfloat16_as_ushort(h10)) | ((uint32_t)__bfloat16_as_ushort(h11) << 16);
            uint32_t r0 = pack2(p00 - __bfloat162float(h00), p01 - __bfloat162float(h01));
            uint32_t r1 = pack2(p10 - __bfloat162float(h10), p11 - __bfloat162float(h11));
            uint32_t off0 = (uint32_t)(m0 + g) * (PSTR * 2) + (uint32_t)kl0 * 2;
            uint32_t off1 = (uint32_t)(m0 + g + 8) * (PSTR * 2) + (uint32_t)kl0 * 2;
            *(uint32_t*)(smem + OFF_P1 + off0) = w0;
            *(uint32_t*)(smem + OFF_P1 + off1) = w1;
            *(uint32_t*)(smem + OFF_P2 + off0) = r0;
            *(uint32_t*)(smem + OFF_P2 + off1) = r1;
        }
        rs0 += __shfl_xor_sync(0xffffffffu, rs0, 1);
        rs0 += __shfl_xor_sync(0xffffffffu, rs0, 2);
        rs1 += __shfl_xor_sync(0xffffffffu, rs1, 1);
        rs1 += __shfl_xor_sync(0xffffffffu, rs1, 2);
        lacc0 += rs0;
        lacc1 += rs1;
        __syncthreads();   // sync2: sP_j + sV_j visible everywhere

        // ---- issue cp.async for K tile j+1 (hidden under PV) ----
        if (j < qt) {
            const uint4* gk1 = gk1b + (size_t)(j + 1) * 2048;
            const uint4* gk2 = gk2b + (size_t)(j + 1) * 2048;
            #pragma unroll
            for (int i = 0; i < 4; i++) {
                int u = tid + 512 * i;
                int row = u >> 5, c16 = u & 31;
                uint32_t off = (uint32_t)row * (KSTR * 2) + (uint32_t)c16 * 16;
                cpasync16(sb + OFF_K1 + off, gk1 + u);
                cpasync16(sb + OFF_K2 + off, gk2 + u);
            }
            CP_COMMIT();
        }

        // ---- O += P1*V1 + P1*V2 + P2*V1 (warp: rows m0, cols nO..nO+64, k=64) ----
        #pragma unroll
        for (int ks = 0; ks < 4; ks++) {
            const uint32_t k0 = ks * 16;
            uint32_t a1[4], a2[4];
            uint32_t aoff = rowA * (PSTR * 2) + (k0 + colA8) * 2;
            ldsm4(a1, sb + OFF_P1 + aoff);
            ldsm4(a2, sb + OFF_P2 + aoff);
            #pragma unroll
            for (int nv = 0; nv < 4; nv++) {
                uint32_t b1[4], b2[4];
                uint32_t boff = (uint32_t)(nO + 16 * nv + rowBl) * (VSTR * 2) + (k0 + colB8) * 2;
                ldsm4(b1, sb + OFF_V1 + boff);
                ldsm4(b2, sb + OFF_V2 + boff);
                mma_bf16(Oacc[2 * nv], a1, b1[0], b1[1]);
                mma_bf16(Oacc[2 * nv], a1, b2[0], b2[1]);
                mma_bf16(Oacc[2 * nv], a2, b1[0], b1[1]);
                mma_bf16(Oacc[2 * nv + 1], a1, b1[2], b1[3]);
                mma_bf16(Oacc[2 * nv + 1], a1, b2[2], b2[3]);
                mma_bf16(Oacc[2 * nv + 1], a2, b1[2], b1[3]);
            }
        }
    }

    // ---- combine l across the 4 col warps, then store O / l ----
    __syncthreads();
    if (t4 == 0) {
        sL[(m0 + g) * 4 + wc] = lacc0;
        sL[(m0 + g + 8) * 4 + wc] = lacc1;
    }
    __syncthreads();
    if (tid < 64) sLt[tid] = sL[tid * 4] + sL[tid * 4 + 1] + sL[tid * 4 + 2] + sL[tid * 4 + 3];
    __syncthreads();

    const float linv0 = 1.0f / sLt[m0 + g];
    const float linv1 = 1.0f / sLt[m0 + g + 8];
    float* gO = O + ((size_t)b * SEQ + (size_t)qt * BQ) * DH;
    const int row0 = m0 + g, row1 = m0 + g + 8;
    #pragma unroll
    for (int nb = 0; nb < 8; nb++) {
        const int col = nO + 8 * nb + 2 * t4;
        float2 v0 = make_float2(Oacc[nb][0] * linv0, Oacc[nb][1] * linv0);
        float2 v1 = make_float2(Oacc[nb][2] * linv1, Oacc[nb][3] * linv1);
        *(float2*)(gO + (size_t)row0 * DH + col) = v0;
        *(float2*)(gO + (size_t)row1 * DH + col) = v1;
    }
}

// ---------------- launch ----------------
extern "C" void kernel_launch(void* const* d_in, const int* in_sizes, int n_in,
                              void* d_out, int out_size)
{
    const float* Q  = (const float*)d_in[0];
    const float* K  = (const float*)d_in[1];
    const float* V  = (const float*)d_in[2];
    const int*   pm = (const int*)d_in[3];
    float* O = (float*)d_out;

    prep<<<dim3(32, 4, 16), 256>>>(K, V);

    cudaFuncSetAttribute(attn_mma, cudaFuncAttributeMaxDynamicSharedMemorySize, SMEM_TOTAL);
    attn_mma<<<dim3(SEQ / BQ, BATCH), 512, SMEM_TOTAL>>>(Q, pm, O);
}

// round 11
// speedup vs baseline: 3.2227x; 1.2185x over previous
#include <cuda_runtime.h>
#include <cuda_fp16.h>
#include <stdint.h>
#include <math.h>

#define BATCH 16
#define SEQ   2048
#define DH    256
#define BQ    64
#define BKT   64
#define QSCALE 0.0625f

// fp16 element strides (rows 16B-aligned, odd multiple of 16B -> conflict-free ldsm)
#define QSTR 264   // 528 B rows
#define KSTR 264
#define VSTR 72    // 144 B rows
#define PSTR 72

// smem byte offsets
#define OFF_PM  0                     // 64 ints (256B)
#define OFF_L   256                   // sL[64][4] float (1024B)
#define OFF_LT  1280                  // sLtot[64] float (256B)
#define OFF_Q1  2048
#define OFF_K1  (OFF_Q1 + 64*QSTR*2)  // +33792
#define OFF_K2  (OFF_K1 + 64*KSTR*2)
#define OFF_V1  (OFF_K2 + 64*KSTR*2)
#define OFF_V2  (OFF_V1 + 256*VSTR*2) // +36864
#define OFF_P1  (OFF_V2 + 256*VSTR*2)
#define SMEM_TOTAL (OFF_P1 + 64*PSTR*2)  // 186368

// ---------------- scratch: fp16 splits, V transposed ----------------
__device__ __half g_K1[BATCH * SEQ * DH];
__device__ __half g_K2[BATCH * SEQ * DH];
__device__ __half g_Vt1[BATCH * DH * SEQ];
__device__ __half g_Vt2[BATCH * DH * SEQ];

// ---------------- helpers ----------------
__device__ __forceinline__ uint32_t smem_u32(const void* p) {
    uint32_t a;
    asm("{ .reg .u64 t; cvta.to.shared.u64 t, %1; cvt.u32.u64 %0, t; }" : "=r"(a) : "l"(p));
    return a;
}
__device__ __forceinline__ uint32_t packh2(float lo, float hi) {
    uint32_t r;
    asm("cvt.rn.f16x2.f32 %0, %1, %2;" : "=r"(r) : "f"(hi), "f"(lo));
    return r;
}
__device__ __forceinline__ void ldsm4(uint32_t r[4], uint32_t addr) {
    asm volatile("ldmatrix.sync.aligned.m8n8.x4.shared.b16 {%0,%1,%2,%3}, [%4];"
                 : "=r"(r[0]), "=r"(r[1]), "=r"(r[2]), "=r"(r[3]) : "r"(addr));
}
__device__ __forceinline__ void mma_f16(float c[4], const uint32_t a[4], uint32_t b0, uint32_t b1) {
    asm volatile("mma.sync.aligned.m16n8k16.row.col.f32.f16.f16.f32 "
                 "{%0,%1,%2,%3}, {%4,%5,%6,%7}, {%8,%9}, {%0,%1,%2,%3};"
                 : "+f"(c[0]), "+f"(c[1]), "+f"(c[2]), "+f"(c[3])
                 : "r"(a[0]), "r"(a[1]), "r"(a[2]), "r"(a[3]), "r"(b0), "r"(b1));
}
__device__ __forceinline__ void cpasync16(uint32_t saddr, const void* gaddr) {
    asm volatile("cp.async.cg.shared.global [%0], [%1], 16;" :: "r"(saddr), "l"(gaddr));
}
#define CP_COMMIT() asm volatile("cp.async.commit_group;" ::: "memory")
#define CP_WAIT0()  asm volatile("cp.async.wait_group 0;" ::: "memory")

// ---------------- merged pre-pass: K fp16 splits + V transposed fp16 splits ----------------
// grid (32, 4, 16), block 256
__global__ void prep(const float* __restrict__ K, const float* __restrict__ V) {
    const int t = threadIdx.x;
    // --- K part ---
    {
        const size_t blk = blockIdx.x + 32 * blockIdx.y + 128 * (size_t)blockIdx.z; // 0..2047
        const float4* k4 = (const float4*)K;
        #pragma unroll
        for (int u = 0; u < 4; u++) {
            size_t i = blk * 1024 + t + 256 * u;
            float4 v = k4[i];
            __half hx = __float2half_rn(v.x), hy = __float2half_rn(v.y);
            __half hz = __float2half_rn(v.z), hw = __float2half_rn(v.w);
            uint2 a, b;
            a.x = ((uint32_t)__half_as_ushort(hx)) | ((uint32_t)__half_as_ushort(hy) << 16);
            a.y = ((uint32_t)__half_as_ushort(hz)) | ((uint32_t)__half_as_ushort(hw) << 16);
            b.x = packh2(v.x - __half2float(hx), v.y - __half2float(hy));
            b.y = packh2(v.z - __half2float(hz), v.w - __half2float(hw));
            ((uint2*)g_K1)[i] = a;
            ((uint2*)g_K2)[i] = b;
        }
    }
    // --- V part: transpose 64x64 tile ---
    __shared__ float s[64][65];
    const int b = blockIdx.z, n0 = blockIdx.x * 64, d0 = blockIdx.y * 64;
    #pragma unroll
    for (int i = 0; i < 16; i++) {
        int e = t + 256 * i, ln = e >> 6, ld = e & 63;
        s[ln][ld] = V[((size_t)b * SEQ + n0 + ln) * DH + d0 + ld];
    }
    __syncthreads();
    #pragma unroll
    for (int i = 0; i < 16; i++) {
        int e = t + 256 * i, dd = e >> 6, nn = e & 63;
        float x = s[nn][dd];
        __half h1 = __float2half_rn(x);
        size_t o = ((size_t)b * DH + d0 + dd) * SEQ + n0 + nn;
        g_Vt1[o] = h1;
        g_Vt2[o] = __float2half_rn(x - __half2float(h1));
    }
}

// ---------------- main kernel: 16-warp fp16 2-term flash attention ----------------
__global__ __launch_bounds__(512, 1)
void attn_mma(const float* __restrict__ Q, const int* __restrict__ pm, float* __restrict__ O)
{
    extern __shared__ char smem[];
    const uint32_t sb = smem_u32(smem);
    const int tid = threadIdx.x, lane = tid & 31, wid = tid >> 5;
    const int wr = wid & 3, wc = wid >> 2;          // 4 x 4 warp grid
    const int qt = 31 - blockIdx.x, b = blockIdx.y;
    int* sPm = (int*)(smem + OFF_PM);
    float* sL = (float*)(smem + OFF_L);
    float* sLt = (float*)(smem + OFF_LT);

    const int m0 = 16 * wr;           // S/O row base
    const int nS = 16 * wc;           // S col base
    const int nO = 64 * wc;           // O col base
    const int g = lane >> 2, t4 = lane & 3;

    // ldmatrix x4 lane-address components
    const uint32_t rowA = (uint32_t)(m0 + (lane & 15));
    const uint32_t colA8 = ((lane >> 4) & 1) << 3;
    const uint32_t rowBl = (uint32_t)((lane & 7) + ((lane >> 1) & 8));
    const uint32_t colB8 = (uint32_t)(lane & 8);

    const uint4* gk1b = (const uint4*)(g_K1 + (size_t)b * SEQ * DH);
    const uint4* gk2b = (const uint4*)(g_K2 + (size_t)b * SEQ * DH);
    const uint4* gv1b = (const uint4*)(g_Vt1 + (size_t)b * DH * SEQ);
    const uint4* gv2b = (const uint4*)(g_Vt2 + (size_t)b * DH * SEQ);

    // ---- prologue: load Q tile, scale, single fp16 into sQ1 ----
    {
        const float4* gQ = (const float4*)(Q + ((size_t)b * SEQ + (size_t)qt * BQ) * DH);
        #pragma unroll
        for (int i = 0; i < 8; i++) {
            int f = tid + 512 * i;          // 0..4095 float4
            int row = f >> 6, c4 = f & 63;
            float4 v = gQ[row * 64 + c4];
            uint2 a1;
            a1.x = packh2(v.x * QSCALE, v.y * QSCALE);
            a1.y = packh2(v.z * QSCALE, v.w * QSCALE);
            uint32_t off = (uint32_t)row * (QSTR * 2) + (uint32_t)c4 * 8;
            *(uint2*)(smem + OFF_Q1 + off) = a1;
        }
    }

    // ---- preload K tile j=0 via cp.async ----
    {
        #pragma unroll
        for (int i = 0; i < 4; i++) {
            int u = tid + 512 * i;            // 0..2047 uint4
            int row = u >> 5, c16 = u & 31;
            uint32_t off = (uint32_t)row * (KSTR * 2) + (uint32_t)c16 * 16;
            cpasync16(sb + OFF_K1 + off, gk1b + u);
            cpasync16(sb + OFF_K2 + off, gk2b + u);
        }
        CP_COMMIT();
    }

    float Oacc[8][4];
    #pragma unroll
    for (int nb = 0; nb < 8; nb++)
        #pragma unroll
        for (int e = 0; e < 4; e++) Oacc[nb][e] = 0.0f;
    float lacc0 = 0.0f, lacc1 = 0.0f;

    for (int j = 0; j <= qt; j++) {
        CP_WAIT0();   // K tile j landed
        if (tid < BKT) sPm[tid] = pm[(size_t)b * SEQ + (size_t)j * BKT + tid];
        __syncthreads();   // sync1: sK_j + sPm visible; all warps done with sV_{j-1}

        // ---- issue cp.async for V tile j (waited after S-phase) ----
        {
            #pragma unroll
            for (int i = 0; i < 4; i++) {
                int u = tid + 512 * i;        // 0..2047 uint4 (256 rows x 8)
                int d = u >> 3, c = u & 7;
                uint32_t off = (uint32_t)d * (VSTR * 2) + (uint32_t)c * 16;
                const uint4* gv1 = gv1b + (size_t)j * (BKT / 8) + (size_t)d * (SEQ / 8) + c;
                const uint4* gv2 = gv2b + (size_t)j * (BKT / 8) + (size_t)d * (SEQ / 8) + c;
                cpasync16(sb + OFF_V1 + off, gv1);
                cpasync16(sb + OFF_V2 + off, gv2);
            }
            CP_COMMIT();
        }

        // ---- S = Q1K1 + Q1K2 (2 terms, fp16) ----
        float Sa[2][4], Sb[2][4];
        #pragma unroll
        for (int nb = 0; nb < 2; nb++)
            #pragma unroll
            for (int e = 0; e < 4; e++) { Sa[nb][e] = 0.0f; Sb[nb][e] = 0.0f; }

        #pragma unroll 4
        for (int ks = 0; ks < 16; ks++) {
            const uint32_t k0 = ks * 16;
            uint32_t a1[4], b1[4], b2[4];
            uint32_t aoff = rowA * (QSTR * 2) + (k0 + colA8) * 2;
            uint32_t boff = (uint32_t)(nS + rowBl) * (KSTR * 2) + (k0 + colB8) * 2;
            ldsm4(a1, sb + OFF_Q1 + aoff);
            ldsm4(b1, sb + OFF_K1 + boff);
            ldsm4(b2, sb + OFF_K2 + boff);
            mma_f16(Sa[0], a1, b1[0], b1[1]);
            mma_f16(Sb[0], a1, b2[0], b2[1]);
            mma_f16(Sa[1], a1, b1[2], b1[3]);
            mma_f16(Sb[1], a1, b2[2], b2[3]);
        }

        CP_WAIT0();   // V tile j landed (S-phase hid the latency)

        // ---- mask + exp(s) + row sums (of quantized P) + P1 to smem ----
        const int qg0 = qt * BQ + m0 + g;
        const int qg1 = qg0 + 8;
        const int kb = j * BKT;
        float rs0 = 0.0f, rs1 = 0.0f;
        #pragma unroll
        for (int nb = 0; nb < 2; nb++) {
            const int kl0 = nS + 8 * nb + 2 * t4;
            const int pm0 = sPm[kl0], pm1 = sPm[kl0 + 1];
            float s00 = Sa[nb][0] + Sb[nb][0];
            float s01 = Sa[nb][1] + Sb[nb][1];
            float s10 = Sa[nb][2] + Sb[nb][2];
            float s11 = Sa[nb][3] + Sb[nb][3];
            float p00 = ((kb + kl0 <= qg0) && pm0) ? __expf(s00) : 0.0f;
            float p01 = ((kb + kl0 + 1 <= qg0) && pm1) ? __expf(s01) : 0.0f;
            float p10 = ((kb + kl0 <= qg1) && pm0) ? __expf(s10) : 0.0f;
            float p11 = ((kb + kl0 + 1 <= qg1) && pm1) ? __expf(s11) : 0.0f;
            __half h00 = __float2half_rn(p00), h01 = __float2half_rn(p01);
            __half h10 = __float2half_rn(p10), h11 = __float2half_rn(p11);
            // l sums the QUANTIZED weights so O/l is an exact weighted average
            rs0 += __half2float(h00) + __half2float(h01);
            rs1 += __half2float(h10) + __half2float(h11);
            uint32_t w0 = ((uint32_t)__half_as_ushort(h00)) | ((uint32_t)__half_as_ushort(h01) << 16);
            uint32_t w1 = ((uint32_t)__half_as_ushort(h10)) | ((uint32_t)__half_as_ushort(h11) << 16);
            uint32_t off0 = (uint32_t)(m0 + g) * (PSTR * 2) + (uint32_t)kl0 * 2;
            uint32_t off1 = (uint32_t)(m0 + g + 8) * (PSTR * 2) + (uint32_t)kl0 * 2;
            *(uint32_t*)(smem + OFF_P1 + off0) = w0;
            *(uint32_t*)(smem + OFF_P1 + off1) = w1;
        }
        rs0 += __shfl_xor_sync(0xffffffffu, rs0, 1);
        rs0 += __shfl_xor_sync(0xffffffffu, rs0, 2);
        rs1 += __shfl_xor_sync(0xffffffffu, rs1, 1);
        rs1 += __shfl_xor_sync(0xffffffffu, rs1, 2);
        lacc0 += rs0;
        lacc1 += rs1;
        __syncthreads();   // sync2: sP_j + sV_j visible everywhere

        // ---- issue cp.async for K tile j+1 (hidden under PV) ----
        if (j < qt) {
            const uint4* gk1 = gk1b + (size_t)(j + 1) * 2048;
            const uint4* gk2 = gk2b + (size_t)(j + 1) * 2048;
            #pragma unroll
            for (int i = 0; i < 4; i++) {
                int u = tid + 512 * i;
                int row = u >> 5, c16 = u & 31;
                uint32_t off = (uint32_t)row * (KSTR * 2) + (uint32_t)c16 * 16;
                cpasync16(sb + OFF_K1 + off, gk1 + u);
                cpasync16(sb + OFF_K2 + off, gk2 + u);
            }
            CP_COMMIT();
        }

        // ---- O += P1*V1 + P1*V2 (2 terms) ----
        #pragma unroll
        for (int ks = 0; ks < 4; ks++) {
            const uint32_t k0 = ks * 16;
            uint32_t a1[4];
            uint32_t aoff = rowA * (PSTR * 2) + (k0 + colA8) * 2;
            ldsm4(a1, sb + OFF_P1 + aoff);
            #pragma unroll
            for (int nv = 0; nv < 4; nv++) {
                uint32_t b1[4], b2[4];
                uint32_t boff = (uint32_t)(nO + 16 * nv + rowBl) * (VSTR * 2) + (k0 + colB8) * 2;
                ldsm4(b1, sb + OFF_V1 + boff);
                ldsm4(b2, sb + OFF_V2 + boff);
                mma_f16(Oacc[2 * nv], a1, b1[0], b1[1]);
                mma_f16(Oacc[2 * nv], a1, b2[0], b2[1]);
                mma_f16(Oacc[2 * nv + 1], a1, b1[2], b1[3]);
                mma_f16(Oacc[2 * nv + 1], a1, b2[2], b2[3]);
            }
        }
    }

    // ---- combine l across the 4 col warps, then store O / l ----
    __syncthreads();
    if (t4 == 0) {
        sL[(m0 + g) * 4 + wc] = lacc0;
        sL[(m0 + g + 8) * 4 + wc] = lacc1;
    }
    __syncthreads();
    if (tid < 64) sLt[tid] = sL[tid * 4] + sL[tid * 4 + 1] + sL[tid * 4 + 2] + sL[tid * 4 + 3];
    __syncthreads();

    const float linv0 = 1.0f / sLt[m0 + g];
    const float linv1 = 1.0f / sLt[m0 + g + 8];
    float* gO = O + ((size_t)b * SEQ + (size_t)qt * BQ) * DH;
    const int row0 = m0 + g, row1 = m0 + g + 8;
    #pragma unroll
    for (int nb = 0; nb < 8; nb++) {
        const int col = nO + 8 * nb + 2 * t4;
        float2 v0 = make_float2(Oacc[nb][0] * linv0, Oacc[nb][1] * linv0);
        float2 v1 = make_float2(Oacc[nb][2] * linv1, Oacc[nb][3] * linv1);
        *(float2*)(gO + (size_t)row0 * DH + col) = v0;
        *(float2*)(gO + (size_t)row1 * DH + col) = v1;
    }
}

// ---------------- launch ----------------
extern "C" void kernel_launch(void* const* d_in, const int* in_sizes, int n_in,
                              void* d_out, int out_size)
{
    const float* Q  = (const float*)d_in[0];
    const float* K  = (const float*)d_in[1];
    const float* V  = (const float*)d_in[2];
    const int*   pm = (const int*)d_in[3];
    float* O = (float*)d_out;

    prep<<<dim3(32, 4, 16), 256>>>(K, V);

    cudaFuncSetAttribute(attn_mma, cudaFuncAttributeMaxDynamicSharedMemorySize, SMEM_TOTAL);
    attn_mma<<<dim3(SEQ / BQ, BATCH), 512, SMEM_TOTAL>>>(Q, pm, O);
}

// round 13
// speedup vs baseline: 4.0622x; 1.2605x over previous
#include <cuda_runtime.h>
#include <cuda_fp16.h>
#include <stdint.h>
#include <math.h>

#define BATCH 16
#define SEQ   2048
#define DH    256
#define BQ    64
#define BKT   64
#define QSCALE 0.0625f

// fp16 element strides (rows 16B-aligned, odd multiple of 16B -> conflict-free ldsm)
#define QSTR 264   // 528 B rows
#define KSTR 264
#define VSTR 72    // 144 B rows
#define PSTR 72

// smem byte offsets
#define OFF_PM  0                     // 64 ints (256B)
#define OFF_L   256                   // sL[64][4] float (1024B)
#define OFF_LT  1280                  // sLtot[64] float (256B)
#define OFF_Q1  2048
#define OFF_K1  (OFF_Q1 + 64*QSTR*2)  // 35840
#define OFF_V1  (OFF_K1 + 64*KSTR*2)  // 69632
#define OFF_V2  (OFF_V1 + 256*VSTR*2) // 106496
#define OFF_P1  (OFF_V2 + 256*VSTR*2) // 143360
#define SMEM_TOTAL (OFF_P1 + 64*PSTR*2)  // 152576

// ---------------- scratch: K fp16, V transposed fp16 splits ----------------
__device__ __half g_K1[BATCH * SEQ * DH];
__device__ __half g_Vt1[BATCH * DH * SEQ];
__device__ __half g_Vt2[BATCH * DH * SEQ];

// ---------------- helpers ----------------
__device__ __forceinline__ uint32_t smem_u32(const void* p) {
    uint32_t a;
    asm("{ .reg .u64 t; cvta.to.shared.u64 t, %1; cvt.u32.u64 %0, t; }" : "=r"(a) : "l"(p));
    return a;
}
__device__ __forceinline__ uint32_t packh2(float lo, float hi) {
    uint32_t r;
    asm("cvt.rn.f16x2.f32 %0, %1, %2;" : "=r"(r) : "f"(hi), "f"(lo));
    return r;
}
__device__ __forceinline__ void ldsm4(uint32_t r[4], uint32_t addr) {
    asm volatile("ldmatrix.sync.aligned.m8n8.x4.shared.b16 {%0,%1,%2,%3}, [%4];"
                 : "=r"(r[0]), "=r"(r[1]), "=r"(r[2]), "=r"(r[3]) : "r"(addr));
}
__device__ __forceinline__ void mma_f16(float c[4], const uint32_t a[4], uint32_t b0, uint32_t b1) {
    asm volatile("mma.sync.aligned.m16n8k16.row.col.f32.f16.f16.f32 "
                 "{%0,%1,%2,%3}, {%4,%5,%6,%7}, {%8,%9}, {%0,%1,%2,%3};"
                 : "+f"(c[0]), "+f"(c[1]), "+f"(c[2]), "+f"(c[3])
                 : "r"(a[0]), "r"(a[1]), "r"(a[2]), "r"(a[3]), "r"(b0), "r"(b1));
}
__device__ __forceinline__ void cpasync16(uint32_t saddr, const void* gaddr) {
    asm volatile("cp.async.cg.shared.global [%0], [%1], 16;" :: "r"(saddr), "l"(gaddr));
}
#define CP_COMMIT() asm volatile("cp.async.commit_group;" ::: "memory")
#define CP_WAIT0()  asm volatile("cp.async.wait_group 0;" ::: "memory")

// ---------------- merged pre-pass: K fp16 + V transposed fp16 splits ----------------
// grid (32, 4, 16), block 256
__global__ void prep(const float* __restrict__ K, const float* __restrict__ V) {
    const int t = threadIdx.x;
    // --- K part: single fp16 ---
    {
        const size_t blk = blockIdx.x + 32 * blockIdx.y + 128 * (size_t)blockIdx.z; // 0..2047
        const float4* k4 = (const float4*)K;
        #pragma unroll
        for (int u = 0; u < 4; u++) {
            size_t i = blk * 1024 + t + 256 * u;
            float4 v = k4[i];
            uint2 a;
            a.x = packh2(v.x, v.y);
            a.y = packh2(v.z, v.w);
            ((uint2*)g_K1)[i] = a;
        }
    }
    // --- V part: transpose 64x64 tile, 2-way split ---
    __shared__ float s[64][65];
    const int b = blockIdx.z, n0 = blockIdx.x * 64, d0 = blockIdx.y * 64;
    #pragma unroll
    for (int i = 0; i < 16; i++) {
        int e = t + 256 * i, ln = e >> 6, ld = e & 63;
        s[ln][ld] = V[((size_t)b * SEQ + n0 + ln) * DH + d0 + ld];
    }
    __syncthreads();
    #pragma unroll
    for (int i = 0; i < 16; i++) {
        int e = t + 256 * i, dd = e >> 6, nn = e & 63;
        float x = s[nn][dd];
        __half h1 = __float2half_rn(x);
        size_t o = ((size_t)b * DH + d0 + dd) * SEQ + n0 + nn;
        g_Vt1[o] = h1;
        g_Vt2[o] = __float2half_rn(x - __half2float(h1));
    }
}

// ---------------- main kernel: 16-warp fp16 flash attention ----------------
__global__ __launch_bounds__(512, 1)
void attn_mma(const float* __restrict__ Q, const int* __restrict__ pm, float* __restrict__ O)
{
    extern __shared__ char smem[];
    const uint32_t sb = smem_u32(smem);
    const int tid = threadIdx.x, lane = tid & 31, wid = tid >> 5;
    const int wr = wid & 3, wc = wid >> 2;          // 4x4 grid for S phase
    const int wr2 = wid & 1, wc2 = wid >> 1;        // 2x8 grid for PV phase
    const int qt = 31 - blockIdx.x, b = blockIdx.y;
    int* sPm = (int*)(smem + OFF_PM);
    float* sL = (float*)(smem + OFF_L);
    float* sLt = (float*)(smem + OFF_LT);

    const int m0 = 16 * wr;           // S row base
    const int nS = 16 * wc;           // S col base
    const int g = lane >> 2, t4 = lane & 3;

    // ldmatrix x4 lane-address components
    const uint32_t rowA = (uint32_t)(m0 + (lane & 15));
    const uint32_t rowP = (uint32_t)(32 * wr2 + (lane & 15));   // PV A rows
    const uint32_t colA8 = ((lane >> 4) & 1) << 3;
    const uint32_t rowBl = (uint32_t)((lane & 7) + ((lane >> 1) & 8));
    const uint32_t colB8 = (uint32_t)(lane & 8);

    const uint4* gk1b = (const uint4*)(g_K1 + (size_t)b * SEQ * DH);
    const uint4* gv1b = (const uint4*)(g_Vt1 + (size_t)b * DH * SEQ);
    const uint4* gv2b = (const uint4*)(g_Vt2 + (size_t)b * DH * SEQ);

    // ---- prologue: load Q tile, scale, single fp16 into sQ1 ----
    {
        const float4* gQ = (const float4*)(Q + ((size_t)b * SEQ + (size_t)qt * BQ) * DH);
        #pragma unroll
        for (int i = 0; i < 8; i++) {
            int f = tid + 512 * i;          // 0..4095 float4
            int row = f >> 6, c4 = f & 63;
            float4 v = gQ[row * 64 + c4];
            uint2 a1;
            a1.x = packh2(v.x * QSCALE, v.y * QSCALE);
            a1.y = packh2(v.z * QSCALE, v.w * QSCALE);
            uint32_t off = (uint32_t)row * (QSTR * 2) + (uint32_t)c4 * 8;
            *(uint2*)(smem + OFF_Q1 + off) = a1;
        }
    }

    // ---- preload K tile j=0 via cp.async ----
    {
        #pragma unroll
        for (int i = 0; i < 4; i++) {
            int u = tid + 512 * i;            // 0..2047 uint4
            int row = u >> 5, c16 = u & 31;
            uint32_t off = (uint32_t)row * (KSTR * 2) + (uint32_t)c16 * 16;
            cpasync16(sb + OFF_K1 + off, gk1b + u);
        }
        CP_COMMIT();
    }

    float Oacc[8][4];                 // [mi*4 + ni], mi: 16-row halves, ni: 8-col frags
    #pragma unroll
    for (int nb = 0; nb < 8; nb++)
        #pragma unroll
        for (int e = 0; e < 4; e++) Oacc[nb][e] = 0.0f;
    float lacc0 = 0.0f, lacc1 = 0.0f;

    for (int j = 0; j <= qt; j++) {
        CP_WAIT0();   // K tile j landed
        if (tid < BKT) sPm[tid] = pm[(size_t)b * SEQ + (size_t)j * BKT + tid];
        __syncthreads();   // sync1: sK_j + sPm visible; all warps done with sV_{j-1}

        // ---- issue cp.async for V tile j (waited after S-phase) ----
        {
            #pragma unroll
            for (int i = 0; i < 4; i++) {
                int u = tid + 512 * i;        // 0..2047 uint4 (256 rows x 8)
                int d = u >> 3, c = u & 7;
                uint32_t off = (uint32_t)d * (VSTR * 2) + (uint32_t)c * 16;
                const uint4* gv1 = gv1b + (size_t)j * (BKT / 8) + (size_t)d * (SEQ / 8) + c;
                const uint4* gv2 = gv2b + (size_t)j * (BKT / 8) + (size_t)d * (SEQ / 8) + c;
                cpasync16(sb + OFF_V1 + off, gv1);
                cpasync16(sb + OFF_V2 + off, gv2);
            }
            CP_COMMIT();
        }

        // ---- S = Q1 * K1 (single term) ----
        float Sa[2][4];
        #pragma unroll
        for (int nb = 0; nb < 2; nb++)
            #pragma unroll
            for (int e = 0; e < 4; e++) Sa[nb][e] = 0.0f;

        #pragma unroll 4
        for (int ks = 0; ks < 16; ks++) {
            const uint32_t k0 = ks * 16;
            uint32_t a1[4], b1[4];
            ldsm4(a1, sb + OFF_Q1 + rowA * (QSTR * 2) + (k0 + colA8) * 2);
            ldsm4(b1, sb + OFF_K1 + (uint32_t)(nS + rowBl) * (KSTR * 2) + (k0 + colB8) * 2);
            mma_f16(Sa[0], a1, b1[0], b1[1]);
            mma_f16(Sa[1], a1, b1[2], b1[3]);
        }

        CP_WAIT0();   // V tile j landed (S-phase hid the latency)

        // ---- mask + exp(s) + row sums (of quantized P) + P1 to smem ----
        const int qg0 = qt * BQ + m0 + g;
        const int qg1 = qg0 + 8;
        const int kb = j * BKT;
        float rs0 = 0.0f, rs1 = 0.0f;
        #pragma unroll
        for (int nb = 0; nb < 2; nb++) {
            const int kl0 = nS + 8 * nb + 2 * t4;
            const int pm0 = sPm[kl0], pm1 = sPm[kl0 + 1];
            float p00 = ((kb + kl0 <= qg0) && pm0) ? __expf(Sa[nb][0]) : 0.0f;
            float p01 = ((kb + kl0 + 1 <= qg0) && pm1) ? __expf(Sa[nb][1]) : 0.0f;
            float p10 = ((kb + kl0 <= qg1) && pm0) ? __expf(Sa[nb][2]) : 0.0f;
            float p11 = ((kb + kl0 + 1 <= qg1) && pm1) ? __expf(Sa[nb][3]) : 0.0f;
            __half h00 = __float2half_rn(p00), h01 = __float2half_rn(p01);
            __half h10 = __float2half_rn(p10), h11 = __float2half_rn(p11);
            // l sums the QUANTIZED weights so O/l is an exact weighted average
            rs0 += __half2float(h00) + __half2float(h01);
            rs1 += __half2float(h10) + __half2float(h11);
            uint32_t w0 = ((uint32_t)__half_as_ushort(h00)) | ((uint32_t)__half_as_ushort(h01) << 16);
            uint32_t w1 = ((uint32_t)__half_as_ushort(h10)) | ((uint32_t)__half_as_ushort(h11) << 16);
            uint32_t off0 = (uint32_t)(m0 + g) * (PSTR * 2) + (uint32_t)kl0 * 2;
            uint32_t off1 = (uint32_t)(m0 + g + 8) * (PSTR * 2) + (uint32_t)kl0 * 2;
            *(uint32_t*)(smem + OFF_P1 + off0) = w0;
            *(uint32_t*)(smem + OFF_P1 + off1) = w1;
        }
        rs0 += __shfl_xor_sync(0xffffffffu, rs0, 1);
        rs0 += __shfl_xor_sync(0xffffffffu, rs0, 2);
        rs1 += __shfl_xor_sync(0xffffffffu, rs1, 1);
        rs1 += __shfl_xor_sync(0xffffffffu, rs1, 2);
        lacc0 += rs0;
        lacc1 += rs1;
        __syncthreads();   // sync2: sP_j + sV_j visible everywhere

        // ---- issue cp.async for K tile j+1 (hidden under PV) ----
        if (j < qt) {
            const uint4* gk1 = gk1b + (size_t)(j + 1) * 2048;
            #pragma unroll
            for (int i = 0; i < 4; i++) {
                int u = tid + 512 * i;
                int row = u >> 5, c16 = u & 31;
                uint32_t off = (uint32_t)row * (KSTR * 2) + (uint32_t)c16 * 16;
                cpasync16(sb + OFF_K1 + off, gk1 + u);
            }
            CP_COMMIT();
        }

        // ---- O += P1*V1 + P1*V2 : warp tile 32 rows x 32 cols ----
        #pragma unroll
        for (int ks = 0; ks < 4; ks++) {
            const uint32_t k0 = ks * 16;
            uint32_t ap0[4], ap1[4];
            ldsm4(ap0, sb + OFF_P1 + rowP * (PSTR * 2) + (k0 + colA8) * 2);
            ldsm4(ap1, sb + OFF_P1 + (rowP + 16) * (PSTR * 2) + (k0 + colA8) * 2);
            #pragma unroll
            for (int v = 0; v < 2; v++) {
                uint32_t vrow = (uint32_t)(32 * wc2 + 16 * v + rowBl);
                uint32_t b1[4], b2[4];
                ldsm4(b1, sb + OFF_V1 + vrow * (VSTR * 2) + (k0 + colB8) * 2);
                ldsm4(b2, sb + OFF_V2 + vrow * (VSTR * 2) + (k0 + colB8) * 2);
                mma_f16(Oacc[2 * v],     ap0, b1[0], b1[1]);
                mma_f16(Oacc[2 * v],     ap0, b2[0], b2[1]);
                mma_f16(Oacc[2 * v + 1], ap0, b1[2], b1[3]);
                mma_f16(Oacc[2 * v + 1], ap0, b2[2], b2[3]);
                mma_f16(Oacc[4 + 2 * v],     ap1, b1[0], b1[1]);
                mma_f16(Oacc[4 + 2 * v],     ap1, b2[0], b2[1]);
                mma_f16(Oacc[4 + 2 * v + 1], ap1, b1[2], b1[3]);
                mma_f16(Oacc[4 + 2 * v + 1], ap1, b2[2], b2[3]);
            }
        }
    }

    // ---- combine l across the 4 S-col warps, then store O / l ----
    __syncthreads();
    if (t4 == 0) {
        sL[(m0 + g) * 4 + wc] = lacc0;
        sL[(m0 + g + 8) * 4 + wc] = lacc1;
    }
    __syncthreads();
    if (tid < 64) sLt[tid] = sL[tid * 4] + sL[tid * 4 + 1] + sL[tid * 4 + 2] + sL[tid * 4 + 3];
    __syncthreads();

    float* gO = O + ((size_t)b * SEQ + (size_t)qt * BQ) * DH;
    #pragma unroll
    for (int mi = 0; mi < 2; mi++) {
        const int r0 = 32 * wr2 + 16 * mi + g;
        const int r1 = r0 + 8;
        const float linv0 = 1.0f / sLt[r0];
        const float linv1 = 1.0f / sLt[r1];
        #pragma unroll
        for (int ni = 0; ni < 4; ni++) {
            const int col = 32 * wc2 + 8 * ni + 2 * t4;
            const float* f = Oacc[mi * 4 + ni];
            *(float2*)(gO + (size_t)r0 * DH + col) = make_float2(f[0] * linv0, f[1] * linv0);
            *(float2*)(gO + (size_t)r1 * DH + col) = make_float2(f[2] * linv1, f[3] * linv1);
        }
    }
}

// ---------------- launch ----------------
extern "C" void kernel_launch(void* const* d_in, const int* in_sizes, int n_in,
                              void* d_out, int out_size)
{
    const float* Q  = (const float*)d_in[0];
    const float* K  = (const float*)d_in[1];
    const float* V  = (const float*)d_in[2];
    const int*   pm = (const int*)d_in[3];
    float* O = (float*)d_out;

    prep<<<dim3(32, 4, 16), 256>>>(K, V);

    cudaFuncSetAttribute(attn_mma, cudaFuncAttributeMaxDynamicSharedMemorySize, SMEM_TOTAL);
    attn_mma<<<dim3(SEQ / BQ, BATCH), 512, SMEM_TOTAL>>>(Q, pm, O);
}

// round 14
// speedup vs baseline: 5.5735x; 1.3720x over previous
#include <cuda_runtime.h>
#include <cuda_fp16.h>
#include <stdint.h>
#include <math.h>

#define BATCH 16
#define SEQ   2048
#define DH    256
#define BQ    64
#define BKT   128
#define QSCALE 0.0625f

// fp16 element strides (rows 16B-aligned, odd multiple of 16B -> conflict-free ldsm)
#define QSTR 264   // 528 B rows (256 fp16 + 8 pad)
#define KSTR 264
#define VSTR 136   // 272 B rows (128 fp16 + 8 pad)
#define PSTR 136

// smem byte offsets
#define OFF_PM  0                      // 128 ints (512B)
#define OFF_L   512                    // sL[64][4] float (1024B)
#define OFF_LT  1536                   // sLtot[64] float (256B)
#define OFF_Q1  2048
#define OFF_K1  (OFF_Q1 + 64*QSTR*2)   // 35840  (K: 128 x 528 = 67584)
#define OFF_V1  (OFF_K1 + 128*KSTR*2)  // 103424 (V: 256 x 272 = 69632)
#define OFF_P1  (OFF_V1 + 256*VSTR*2)  // 173056 (P: 64 x 272 = 17408)
#define SMEM_TOTAL (OFF_P1 + 64*PSTR*2)   // 190464

// ---------------- scratch: K fp16, V transposed fp16 ----------------
__device__ __half g_K1[BATCH * SEQ * DH];
__device__ __half g_Vt1[BATCH * DH * SEQ];

// ---------------- helpers ----------------
__device__ __forceinline__ uint32_t smem_u32(const void* p) {
    uint32_t a;
    asm("{ .reg .u64 t; cvta.to.shared.u64 t, %1; cvt.u32.u64 %0, t; }" : "=r"(a) : "l"(p));
    return a;
}
__device__ __forceinline__ uint32_t packh2(float lo, float hi) {
    uint32_t r;
    asm("cvt.rn.f16x2.f32 %0, %1, %2;" : "=r"(r) : "f"(hi), "f"(lo));
    return r;
}
__device__ __forceinline__ void ldsm4(uint32_t r[4], uint32_t addr) {
    asm volatile("ldmatrix.sync.aligned.m8n8.x4.shared.b16 {%0,%1,%2,%3}, [%4];"
                 : "=r"(r[0]), "=r"(r[1]), "=r"(r[2]), "=r"(r[3]) : "r"(addr));
}
__device__ __forceinline__ void mma_f16(float c[4], const uint32_t a[4], uint32_t b0, uint32_t b1) {
    asm volatile("mma.sync.aligned.m16n8k16.row.col.f32.f16.f16.f32 "
                 "{%0,%1,%2,%3}, {%4,%5,%6,%7}, {%8,%9}, {%0,%1,%2,%3};"
                 : "+f"(c[0]), "+f"(c[1]), "+f"(c[2]), "+f"(c[3])
                 : "r"(a[0]), "r"(a[1]), "r"(a[2]), "r"(a[3]), "r"(b0), "r"(b1));
}
__device__ __forceinline__ void cpasync16(uint32_t saddr, const void* gaddr) {
    asm volatile("cp.async.cg.shared.global [%0], [%1], 16;" :: "r"(saddr), "l"(gaddr));
}
#define CP_COMMIT() asm volatile("cp.async.commit_group;" ::: "memory")
#define CP_WAIT0()  asm volatile("cp.async.wait_group 0;" ::: "memory")

// ---------------- merged pre-pass: K fp16 + V transposed fp16 ----------------
// grid (32, 4, 16), block 256
__global__ void prep(const float* __restrict__ K, const float* __restrict__ V) {
    const int t = threadIdx.x;
    // --- K part: single fp16 ---
    {
        const size_t blk = blockIdx.x + 32 * blockIdx.y + 128 * (size_t)blockIdx.z; // 0..2047
        const float4* k4 = (const float4*)K;
        #pragma unroll
        for (int u = 0; u < 4; u++) {
            size_t i = blk * 1024 + t + 256 * u;
            float4 v = k4[i];
            uint2 a;
            a.x = packh2(v.x, v.y);
            a.y = packh2(v.z, v.w);
            ((uint2*)g_K1)[i] = a;
        }
    }
    // --- V part: transpose 64x64 tile, single fp16 ---
    __shared__ float s[64][65];
    const int b = blockIdx.z, n0 = blockIdx.x * 64, d0 = blockIdx.y * 64;
    #pragma unroll
    for (int i = 0; i < 16; i++) {
        int e = t + 256 * i, ln = e >> 6, ld = e & 63;
        s[ln][ld] = V[((size_t)b * SEQ + n0 + ln) * DH + d0 + ld];
    }
    __syncthreads();
    #pragma unroll
    for (int i = 0; i < 16; i++) {
        int e = t + 256 * i, dd = e >> 6, nn = e & 63;
        g_Vt1[((size_t)b * DH + d0 + dd) * SEQ + n0 + nn] = __float2half_rn(s[nn][dd]);
    }
}

// ---------------- main kernel: 16-warp fp16 flash attention, BKT=128 ----------------
__global__ __launch_bounds__(512, 1)
void attn_mma(const float* __restrict__ Q, const int* __restrict__ pm, float* __restrict__ O)
{
    extern __shared__ char smem[];
    const uint32_t sb = smem_u32(smem);
    const int tid = threadIdx.x, lane = tid & 31, wid = tid >> 5;
    const int wr = wid & 3, wc = wid >> 2;          // 4x4 grid for S phase (16x32 tiles)
    const int wr2 = wid & 1, wc2 = wid >> 1;        // 2x8 grid for PV phase (32x32 tiles)
    const int qt = 31 - blockIdx.x, b = blockIdx.y;
    int* sPm = (int*)(smem + OFF_PM);
    float* sL = (float*)(smem + OFF_L);
    float* sLt = (float*)(smem + OFF_LT);

    const int m0 = 16 * wr;           // S row base
    const int nS = 32 * wc;           // S col base (32 cols per warp)
    const int g = lane >> 2, t4 = lane & 3;

    // ldmatrix x4 lane-address components
    const uint32_t rowA = (uint32_t)(m0 + (lane & 15));
    const uint32_t rowP = (uint32_t)(32 * wr2 + (lane & 15));   // PV A rows
    const uint32_t colA8 = ((lane >> 4) & 1) << 3;
    const uint32_t rowBl = (uint32_t)((lane & 7) + ((lane >> 1) & 8));
    const uint32_t colB8 = (uint32_t)(lane & 8);

    const uint4* gk1b = (const uint4*)(g_K1 + (size_t)b * SEQ * DH);
    const uint4* gv1b = (const uint4*)(g_Vt1 + (size_t)b * DH * SEQ);

    // ---- prologue: load Q tile, scale, single fp16 into sQ1 ----
    {
        const float4* gQ = (const float4*)(Q + ((size_t)b * SEQ + (size_t)qt * BQ) * DH);
        #pragma unroll
        for (int i = 0; i < 8; i++) {
            int f = tid + 512 * i;          // 0..4095 float4
            int row = f >> 6, c4 = f & 63;
            float4 v = gQ[row * 64 + c4];
            uint2 a1;
            a1.x = packh2(v.x * QSCALE, v.y * QSCALE);
            a1.y = packh2(v.z * QSCALE, v.w * QSCALE);
            *(uint2*)(smem + OFF_Q1 + (uint32_t)row * (QSTR * 2) + (uint32_t)c4 * 8) = a1;
        }
    }

    // ---- preload K tile j=0 via cp.async (128 x 256 fp16 = 4096 uint4) ----
    {
        #pragma unroll
        for (int i = 0; i < 8; i++) {
            int u = tid + 512 * i;
            int row = u >> 5, c16 = u & 31;
            cpasync16(sb + OFF_K1 + (uint32_t)row * (KSTR * 2) + (uint32_t)c16 * 16, gk1b + u);
        }
        CP_COMMIT();
    }

    float Oacc[8][4];                 // [mi*4 + ni]
    #pragma unroll
    for (int nb = 0; nb < 8; nb++)
        #pragma unroll
        for (int e = 0; e < 4; e++) Oacc[nb][e] = 0.0f;
    float lacc0 = 0.0f, lacc1 = 0.0f;

    const int jmax = qt >> 1;         // ceil((qt+1)*64 / 128) - 1

    for (int j = 0; j <= jmax; j++) {
        CP_WAIT0();   // K tile j landed
        if (tid < BKT) sPm[tid] = pm[(size_t)b * SEQ + (size_t)j * BKT + tid];
        __syncthreads();   // sync1: sK_j + sPm visible; all warps done with sV_{j-1}

        // ---- issue cp.async for V tile j (256 rows x 128 cols = 4096 uint4) ----
        {
            #pragma unroll
            for (int i = 0; i < 8; i++) {
                int u = tid + 512 * i;
                int d = u >> 4, c = u & 15;
                cpasync16(sb + OFF_V1 + (uint32_t)d * (VSTR * 2) + (uint32_t)c * 16,
                          gv1b + (size_t)d * (SEQ / 8) + (size_t)j * 16 + c);
            }
            CP_COMMIT();
        }

        // ---- S = Q1 * K1 : warp tile 16 x 32 ----
        float Sa[4][4];
        #pragma unroll
        for (int nb = 0; nb < 4; nb++)
            #pragma unroll
            for (int e = 0; e < 4; e++) Sa[nb][e] = 0.0f;

        #pragma unroll 4
        for (int ks = 0; ks < 16; ks++) {
            const uint32_t k0 = ks * 16;
            uint32_t a1[4];
            ldsm4(a1, sb + OFF_Q1 + rowA * (QSTR * 2) + (k0 + colA8) * 2);
            #pragma unroll
            for (int np = 0; np < 2; np++) {
                uint32_t b1[4];
                ldsm4(b1, sb + OFF_K1 + (uint32_t)(nS + 16 * np + rowBl) * (KSTR * 2) + (k0 + colB8) * 2);
                mma_f16(Sa[2 * np],     a1, b1[0], b1[1]);
                mma_f16(Sa[2 * np + 1], a1, b1[2], b1[3]);
            }
        }

        CP_WAIT0();   // V tile j landed (S-phase hid the latency)

        // ---- mask + exp(s) + row sums (of quantized P) + P1 to smem ----
        const int qg0 = qt * BQ + m0 + g;
        const int qg1 = qg0 + 8;
        const int kb = j * BKT;
        float rs0 = 0.0f, rs1 = 0.0f;
        #pragma unroll
        for (int nb = 0; nb < 4; nb++) {
            const int kl0 = nS + 8 * nb + 2 * t4;
            const int pm0 = sPm[kl0], pm1 = sPm[kl0 + 1];
            float p00 = ((kb + kl0 <= qg0) && pm0) ? __expf(Sa[nb][0]) : 0.0f;
            float p01 = ((kb + kl0 + 1 <= qg0) && pm1) ? __expf(Sa[nb][1]) : 0.0f;
            float p10 = ((kb + kl0 <= qg1) && pm0) ? __expf(Sa[nb][2]) : 0.0f;
            float p11 = ((kb + kl0 + 1 <= qg1) && pm1) ? __expf(Sa[nb][3]) : 0.0f;
            __half h00 = __float2half_rn(p00), h01 = __float2half_rn(p01);
            __half h10 = __float2half_rn(p10), h11 = __float2half_rn(p11);
            // l sums the QUANTIZED weights so O/l is an exact weighted average
            rs0 += __half2float(h00) + __half2float(h01);
            rs1 += __half2float(h10) + __half2float(h11);
            uint32_t w0 = ((uint32_t)__half_as_ushort(h00)) | ((uint32_t)__half_as_ushort(h01) << 16);
            uint32_t w1 = ((uint32_t)__half_as_ushort(h10)) | ((uint32_t)__half_as_ushort(h11) << 16);
            *(uint32_t*)(smem + OFF_P1 + (uint32_t)(m0 + g) * (PSTR * 2) + (uint32_t)kl0 * 2) = w0;
            *(uint32_t*)(smem + OFF_P1 + (uint32_t)(m0 + g + 8) * (PSTR * 2) + (uint32_t)kl0 * 2) = w1;
        }
        rs0 += __shfl_xor_sync(0xffffffffu, rs0, 1);
        rs0 += __shfl_xor_sync(0xffffffffu, rs0, 2);
        rs1 += __shfl_xor_sync(0xffffffffu, rs1, 1);
        rs1 += __shfl_xor_sync(0xffffffffu, rs1, 2);
        lacc0 += rs0;
        lacc1 += rs1;
        __syncthreads();   // sync2: sP_j + sV_j visible everywhere

        // ---- issue cp.async for K tile j+1 (hidden under PV) ----
        if (j < jmax) {
            const uint4* gk1 = gk1b + (size_t)(j + 1) * 4096;
            #pragma unroll
            for (int i = 0; i < 8; i++) {
                int u = tid + 512 * i;
                int row = u >> 5, c16 = u & 31;
                cpasync16(sb + OFF_K1 + (uint32_t)row * (KSTR * 2) + (uint32_t)c16 * 16, gk1 + u);
            }
            CP_COMMIT();
        }

        // ---- O += P1 * V1 : warp tile 32 rows x 32 cols, k = 128 ----
        #pragma unroll
        for (int ks = 0; ks < 8; ks++) {
            const uint32_t k0 = ks * 16;
            uint32_t ap0[4], ap1[4];
            ldsm4(ap0, sb + OFF_P1 + rowP * (PSTR * 2) + (k0 + colA8) * 2);
            ldsm4(ap1, sb + OFF_P1 + (rowP + 16) * (PSTR * 2) + (k0 + colA8) * 2);
            #pragma unroll
            for (int v = 0; v < 2; v++) {
                uint32_t vrow = (uint32_t)(32 * wc2 + 16 * v + rowBl);
                uint32_t b1[4];
                ldsm4(b1, sb + OFF_V1 + vrow * (VSTR * 2) + (k0 + colB8) * 2);
                mma_f16(Oacc[2 * v],         ap0, b1[0], b1[1]);
                mma_f16(Oacc[2 * v + 1],     ap0, b1[2], b1[3]);
                mma_f16(Oacc[4 + 2 * v],     ap1, b1[0], b1[1]);
                mma_f16(Oacc[4 + 2 * v + 1], ap1, b1[2], b1[3]);
            }
        }
    }

    // ---- combine l across the 4 S-col warps, then store O / l ----
    __syncthreads();
    if (t4 == 0) {
        sL[(m0 + g) * 4 + wc] = lacc0;
        sL[(m0 + g + 8) * 4 + wc] = lacc1;
    }
    __syncthreads();
    if (tid < 64) sLt[tid] = sL[tid * 4] + sL[tid * 4 + 1] + sL[tid * 4 + 2] + sL[tid * 4 + 3];
    __syncthreads();

    float* gO = O + ((size_t)b * SEQ + (size_t)qt * BQ) * DH;
    #pragma unroll
    for (int mi = 0; mi < 2; mi++) {
        const int r0 = 32 * wr2 + 16 * mi + g;
        const int r1 = r0 + 8;
        const float linv0 = 1.0f / sLt[r0];
        const float linv1 = 1.0f / sLt[r1];
        #pragma unroll
        for (int ni = 0; ni < 4; ni++) {
            const int col = 32 * wc2 + 8 * ni + 2 * t4;
            const float* f = Oacc[mi * 4 + ni];
            *(float2*)(gO + (size_t)r0 * DH + col) = make_float2(f[0] * linv0, f[1] * linv0);
            *(float2*)(gO + (size_t)r1 * DH + col) = make_float2(f[2] * linv1, f[3] * linv1);
        }
    }
}

// ---------------- launch ----------------
extern "C" void kernel_launch(void* const* d_in, const int* in_sizes, int n_in,
                              void* d_out, int out_size)
{
    const float* Q  = (const float*)d_in[0];
    const float* K  = (const float*)d_in[1];
    const float* V  = (const float*)d_in[2];
    const int*   pm = (const int*)d_in[3];
    float* O = (float*)d_out;

    prep<<<dim3(32, 4, 16), 256>>>(K, V);

    cudaFuncSetAttribute(attn_mma, cudaFuncAttributeMaxDynamicSharedMemorySize, SMEM_TOTAL);
    attn_mma<<<dim3(SEQ / BQ, BATCH), 512, SMEM_TOTAL>>>(Q, pm, O);
}